// round 5
// baseline (speedup 1.0000x reference)
#include <cuda_runtime.h>
#include <cuda_bf16.h>
#include <math.h>

#define NN 4096
#define EE 131072
#define DIN 72
#define DD 256
#define HH 8
#define HDD 32
#define DEMB 128
#define TT 5

// ---------------- scratch (device globals; no runtime allocation) ----------------
__device__ float g_h  [NN * DD];       // running node features x
__device__ float g_pre[NN * DD];       // GIN pre-MLP input (also serves as agg target)
__device__ float g_t  [NN * 768];      // big temp: qkv(768) / mlp hidden(256) / ffn hidden(512)
__device__ float g_t2 [NN * DD];       // temp for LN input
__device__ float g_ao [NN * DD];       // attention output (head-concat)
__device__ float g_emb[NN * DEMB];     // head hidden

// ---------------- activations ----------------
__device__ __forceinline__ float act_elu(float v) {
    return v > 0.f ? v : expm1f(v);
}
__device__ __forceinline__ float act_gelu_tanh(float v) {
    // jax.nn.gelu default (approximate=True)
    const float c = 0.7978845608028654f;   // sqrt(2/pi)
    float u = c * (v + 0.044715f * v * v * v);
    return 0.5f * v * (1.f + tanhf(u));
}

// ---------------- generic tiled SGEMM: C = act(A @ W^T + b) ----------------
// A: [M, K] row-major, W: [Nout, K] row-major (torch Linear weight), C: [M, Nout]
// ACT: 0 = none, 1 = elu, 2 = gelu(tanh)
template <int ACT>
__global__ __launch_bounds__(256)
void gemm_kernel(const float* __restrict__ A, const float* __restrict__ W,
                 const float* __restrict__ bias, float* __restrict__ C,
                 int M, int Nout, int K)
{
    __shared__ float As[16][64];
    __shared__ float Bs[16][64];
    const int tid = threadIdx.x;
    const int tx = tid & 15, ty = tid >> 4;
    const int m0 = blockIdx.y * 64, n0 = blockIdx.x * 64;

    float acc[4][4] = {};

    for (int k0 = 0; k0 < K; k0 += 16) {
        #pragma unroll
        for (int i = tid; i < 1024; i += 256) {
            int r = i >> 4, kk = i & 15;
            int k = k0 + kk;
            As[kk][r] = (k < K) ? A[(m0 + r) * K + k] : 0.f;
            int n = n0 + r;
            Bs[kk][r] = (n < Nout && k < K) ? W[n * K + k] : 0.f;
        }
        __syncthreads();
        #pragma unroll
        for (int kk = 0; kk < 16; kk++) {
            float4 a = *(const float4*)&As[kk][ty * 4];
            float4 b = *(const float4*)&Bs[kk][tx * 4];
            float av[4] = {a.x, a.y, a.z, a.w};
            float bv[4] = {b.x, b.y, b.z, b.w};
            #pragma unroll
            for (int i = 0; i < 4; i++)
                #pragma unroll
                for (int j = 0; j < 4; j++)
                    acc[i][j] += av[i] * bv[j];
        }
        __syncthreads();
    }

    #pragma unroll
    for (int i = 0; i < 4; i++) {
        int m = m0 + ty * 4 + i;
        #pragma unroll
        for (int j = 0; j < 4; j++) {
            int n = n0 + tx * 4 + j;
            if (n < Nout) {
                float v = acc[i][j] + bias[n];
                if (ACT == 1) v = act_elu(v);
                if (ACT == 2) v = act_gelu_tanh(v);
                C[m * Nout + n] = v;
            }
        }
    }
}

// ---------------- GIN pre-init: pre = (1+eps)*x ----------------
__global__ __launch_bounds__(256)
void gin_init_kernel(const float* __restrict__ x, const float* __restrict__ gin_eps,
                     int l, float* __restrict__ pre)
{
    int i = (blockIdx.x * blockDim.x + threadIdx.x) * 4;
    float s = 1.f + gin_eps[l];
    float4 xv = *(const float4*)&x[i];
    float4 r;
    r.x = s * xv.x; r.y = s * xv.y; r.z = s * xv.z; r.w = s * xv.w;
    *(float4*)&pre[i] = r;
}

// ---------------- GIN edge aggregation: pre[dst] += x[src] ----------------
// edge_index arrives as int32 (harness converts int64 inputs), layout [2, E].
__global__ __launch_bounds__(256)
void gin_agg_kernel(const int* __restrict__ ei,
                    const float* __restrict__ x, float* __restrict__ pre)
{
    long long gid = (long long)blockIdx.x * blockDim.x + threadIdx.x;
    int e = (int)(gid >> 6);
    int c = ((int)gid & 63) * 4;
    if (e >= EE) return;
    int src = ei[e];
    int dst = ei[EE + e];
    float4 v = *(const float4*)&x[src * DD + c];
    float* a = &pre[dst * DD + c];
    atomicAdd(a + 0, v.x);
    atomicAdd(a + 1, v.y);
    atomicAdd(a + 2, v.z);
    atomicAdd(a + 3, v.w);
}

// ---------------- fused LayerNorm (+opt ELU) + residual: x += act(LN(in)) ----------------
template <int ACT>
__global__ __launch_bounds__(256)
void ln_res_kernel(const float* __restrict__ in, const float* __restrict__ g,
                   const float* __restrict__ b, float* __restrict__ x)
{
    __shared__ float red[256];
    int row = blockIdx.x, tid = threadIdx.x;
    float v = in[row * DD + tid];

    red[tid] = v;
    __syncthreads();
    #pragma unroll
    for (int s = 128; s > 0; s >>= 1) {
        if (tid < s) red[tid] += red[tid + s];
        __syncthreads();
    }
    float mu = red[0] * (1.f / DD);
    __syncthreads();

    float d = v - mu;
    red[tid] = d * d;
    __syncthreads();
    #pragma unroll
    for (int s = 128; s > 0; s >>= 1) {
        if (tid < s) red[tid] += red[tid + s];
        __syncthreads();
    }
    float var = red[0] * (1.f / DD);

    float y = d * rsqrtf(var + 1e-5f) * g[tid] + b[tid];
    if (ACT == 1) y = act_elu(y);
    x[row * DD + tid] += y;
}

// ---------------- flash attention (fp32, online softmax) ----------------
// qkv: [N, 768] with q|k|v blocks of 256; head h occupies cols h*32..h*32+31.
// out: [N, 256] head-concat. grid = (N/64, H), block = 256.
// Thread t handles query row (t>>2). Its lane quad (t&3) covers the 64 keys
// with an INTERLEAVED stride-4 assignment (row = lane4 + 4*j): keeps the 4
// distinct K-rows per warp instruction on disjoint banks with the 36-float
// (16B-aligned) row pitch. Output dims split into 8-dim strips per lane.
__global__ __launch_bounds__(256)
void flash_kernel(const float* __restrict__ qkv, float* __restrict__ out)
{
    __shared__ float Ks[64][36];   // pitch 144B: 16B-aligned rows for float4
    __shared__ float Vs[64][36];
    __shared__ float Ss[64][65];

    const int tid = threadIdx.x;
    const int hh = blockIdx.y;
    const int q0 = blockIdx.x * 64;
    const int row = tid >> 2;
    const int lane4 = tid & 3;
    const int d0 = lane4 * 8;
    const float scale = 0.17677669529663689f;  // 1/sqrt(32)

    // Q row in registers (4x redundant across the lane quad; one-time cost)
    float q[32];
    #pragma unroll
    for (int d = 0; d < 32; d++)
        q[d] = qkv[(q0 + row) * 768 + hh * 32 + d];

    float m = -1e30f, l = 0.f;
    float o[8] = {0, 0, 0, 0, 0, 0, 0, 0};

    for (int t0 = 0; t0 < NN; t0 += 64) {
        __syncthreads();  // protects Ks/Vs/Ss reuse across iterations
        for (int i = tid; i < 2048; i += 256) {
            int r = i >> 5, d = i & 31;
            Ks[r][d] = qkv[(t0 + r) * 768 + 256 + hh * 32 + d];
            Vs[r][d] = qkv[(t0 + r) * 768 + 512 + hh * 32 + d];
        }
        __syncthreads();

        // S strip (interleaved rows lane4, lane4+4, ...) + running max
        float smax = -1e30f;
        #pragma unroll 4
        for (int j = 0; j < 16; j++) {
            const int kj = lane4 + 4 * j;
            const float* kr = Ks[kj];
            float s = 0.f;
            #pragma unroll
            for (int d = 0; d < 32; d += 4) {
                float4 k4 = *(const float4*)&kr[d];
                s += q[d] * k4.x + q[d + 1] * k4.y + q[d + 2] * k4.z + q[d + 3] * k4.w;
            }
            s *= scale;
            Ss[row][kj] = s;
            smax = fmaxf(smax, s);
        }
        smax = fmaxf(smax, __shfl_xor_sync(0xffffffffu, smax, 1));
        smax = fmaxf(smax, __shfl_xor_sync(0xffffffffu, smax, 2));

        float newm = fmaxf(m, smax);
        float alpha = __expf(m - newm);

        float psum = 0.f;
        #pragma unroll 4
        for (int j = 0; j < 16; j++) {
            const int kj = lane4 + 4 * j;
            float p = __expf(Ss[row][kj] - newm);
            Ss[row][kj] = p;
            psum += p;
        }
        psum += __shfl_xor_sync(0xffffffffu, psum, 1);
        psum += __shfl_xor_sync(0xffffffffu, psum, 2);

        l = l * alpha + psum;
        m = newm;

        #pragma unroll
        for (int d = 0; d < 8; d++) o[d] *= alpha;

        // ensure the quad's Ss writes are visible before cross-lane reads
        __syncwarp();

        #pragma unroll 8
        for (int j = 0; j < 64; j++) {
            float p = Ss[row][j];
            float4 v0 = *(const float4*)&Vs[j][d0];
            float4 v1 = *(const float4*)&Vs[j][d0 + 4];
            o[0] += p * v0.x; o[1] += p * v0.y; o[2] += p * v0.z; o[3] += p * v0.w;
            o[4] += p * v1.x; o[5] += p * v1.y; o[6] += p * v1.z; o[7] += p * v1.w;
        }
    }

    float inv = 1.f / l;
    #pragma unroll
    for (int d = 0; d < 8; d++)
        out[(q0 + row) * DD + hh * 32 + d0 + d] = o[d] * inv;
}

// ---------------- host orchestration ----------------
extern "C" void kernel_launch(void* const* d_in, const int* in_sizes, int n_in,
                              void* d_out, int out_size)
{
    const float*     x         = (const float*)d_in[0];
    const int*       ei        = (const int*)d_in[1];   // int64 in reference -> int32 here
    const float*     in_w      = (const float*)d_in[2];
    const float*     in_b      = (const float*)d_in[3];
    const float*     head_w1   = (const float*)d_in[4];
    const float*     head_b1   = (const float*)d_in[5];
    const float*     head_w2   = (const float*)d_in[6];
    const float*     head_b2   = (const float*)d_in[7];
    const float*     mlp_w1    = (const float*)d_in[8];
    const float*     mlp_b1    = (const float*)d_in[9];
    const float*     mlp_w2    = (const float*)d_in[10];
    const float*     mlp_b2    = (const float*)d_in[11];
    const float*     gin_eps   = (const float*)d_in[12];
    const float*     ln1_g     = (const float*)d_in[13];
    const float*     ln1_b     = (const float*)d_in[14];
    const float*     attn_in_w = (const float*)d_in[15];
    const float*     attn_in_b = (const float*)d_in[16];
    const float*     attn_out_w= (const float*)d_in[17];
    const float*     attn_out_b= (const float*)d_in[18];
    const float*     ln2_g     = (const float*)d_in[19];
    const float*     ln2_b     = (const float*)d_in[20];
    const float*     ffn_w1    = (const float*)d_in[21];
    const float*     ffn_b1    = (const float*)d_in[22];
    const float*     ffn_w2    = (const float*)d_in[23];
    const float*     ffn_b2    = (const float*)d_in[24];
    const float*     ln3_g     = (const float*)d_in[25];
    const float*     ln3_b     = (const float*)d_in[26];

    float *h, *pre, *t, *t2, *ao, *emb;
    cudaGetSymbolAddress((void**)&h,   g_h);
    cudaGetSymbolAddress((void**)&pre, g_pre);
    cudaGetSymbolAddress((void**)&t,   g_t);
    cudaGetSymbolAddress((void**)&t2,  g_t2);
    cudaGetSymbolAddress((void**)&ao,  g_ao);
    cudaGetSymbolAddress((void**)&emb, g_emb);

    // input proj + ELU: [4096,72] -> [4096,256]
    gemm_kernel<1><<<dim3(DD / 64, NN / 64), 256>>>(x, in_w, in_b, h, NN, DD, DIN);

    for (int l = 0; l < 2; l++) {
        // ---- GIN: pre = (1+eps)*x, then pre[dst] += x[src] via atomics ----
        gin_init_kernel<<<(NN * DD / 4) / 256, 256>>>(h, gin_eps, l, pre);
        gin_agg_kernel<<<(EE * 64) / 256, 256>>>(ei, h, pre);
        gemm_kernel<1><<<dim3(DD / 64, NN / 64), 256>>>(
            pre, mlp_w1 + (size_t)l * DD * DD, mlp_b1 + (size_t)l * DD, t, NN, DD, DD);
        gemm_kernel<0><<<dim3(DD / 64, NN / 64), 256>>>(
            t, mlp_w2 + (size_t)l * DD * DD, mlp_b2 + (size_t)l * DD, t2, NN, DD, DD);
        ln_res_kernel<1><<<NN, 256>>>(t2, ln1_g + (size_t)l * DD, ln1_b + (size_t)l * DD, h);

        // ---- global attention ----
        gemm_kernel<0><<<dim3(768 / 64, NN / 64), 256>>>(
            h, attn_in_w + (size_t)l * 768 * DD, attn_in_b + (size_t)l * 768, t, NN, 768, DD);
        flash_kernel<<<dim3(NN / 64, HH), 256>>>(t, ao);
        gemm_kernel<0><<<dim3(DD / 64, NN / 64), 256>>>(
            ao, attn_out_w + (size_t)l * DD * DD, attn_out_b + (size_t)l * DD, t2, NN, DD, DD);
        ln_res_kernel<0><<<NN, 256>>>(t2, ln2_g + (size_t)l * DD, ln2_b + (size_t)l * DD, h);

        // ---- FFN ----
        gemm_kernel<2><<<dim3(512 / 64, NN / 64), 256>>>(
            h, ffn_w1 + (size_t)l * 512 * DD, ffn_b1 + (size_t)l * 512, t, NN, 512, DD);
        gemm_kernel<0><<<dim3(DD / 64, NN / 64), 256>>>(
            t, ffn_w2 + (size_t)l * DD * 512, ffn_b2 + (size_t)l * DD, t2, NN, DD, 512);
        ln_res_kernel<0><<<NN, 256>>>(t2, ln3_g + (size_t)l * DD, ln3_b + (size_t)l * DD, h);
    }

    // ---- head ----
    gemm_kernel<1><<<dim3(DEMB / 64, NN / 64), 256>>>(h, head_w1, head_b1, emb, NN, DEMB, DD);
    gemm_kernel<0><<<dim3(1, NN / 64), 256>>>(emb, head_w2, head_b2, (float*)d_out, NN, TT, DEMB);
}

// round 6
// speedup vs baseline: 1.0958x; 1.0958x over previous
#include <cuda_runtime.h>
#include <cuda_bf16.h>
#include <math.h>

#define NN 4096
#define EE 131072
#define DIN 72
#define DD 256
#define HH 8
#define HDD 32
#define DEMB 128
#define TT 5

// ---------------- scratch (device globals; no runtime allocation) ----------------
__device__ float g_h  [NN * DD];
__device__ float g_pre[NN * DD];
__device__ float g_t  [NN * 768];
__device__ float g_t2 [NN * DD];
__device__ float g_ao [NN * DD];
__device__ float g_emb[NN * DEMB];

// ---------------- f32x2 packed helpers (exact fp32 semantics, 2 FMA / inst) ----------------
__device__ __forceinline__ unsigned long long pack2(float lo, float hi) {
    unsigned long long r;
    asm("mov.b64 %0, {%1, %2};" : "=l"(r) : "f"(lo), "f"(hi));
    return r;
}
__device__ __forceinline__ void unpack2(unsigned long long v, float& lo, float& hi) {
    asm("mov.b64 {%0, %1}, %2;" : "=f"(lo), "=f"(hi) : "l"(v));
}
__device__ __forceinline__ void ffma2(unsigned long long& d, unsigned long long a,
                                      unsigned long long b) {
    asm("fma.rn.f32x2 %0, %1, %2, %0;" : "+l"(d) : "l"(a), "l"(b));
}
__device__ __forceinline__ void fmul2(unsigned long long& d, unsigned long long a,
                                      unsigned long long b) {
    asm("mul.rn.f32x2 %0, %1, %2;" : "=l"(d) : "l"(a), "l"(b));
}

// ---------------- activations ----------------
__device__ __forceinline__ float act_elu(float v) {
    return v > 0.f ? v : expm1f(v);
}
__device__ __forceinline__ float act_gelu_tanh(float v) {
    const float c = 0.7978845608028654f;   // sqrt(2/pi)
    float u = c * (v + 0.044715f * v * v * v);
    return 0.5f * v * (1.f + tanhf(u));
}

// ---------------- f32x2 SGEMM: C = act(A @ W^T + b) ----------------
// BM=64, BN=128, BK=8, 256 threads, per-thread 4x8 (cols split 4+4 at +64).
// Requires: M%64==0, Nout%128==0, K%8==0 (true for all call sites using it).
template <int ACT>
__global__ __launch_bounds__(256)
void gemm_f2_kernel(const float* __restrict__ A, const float* __restrict__ W,
                    const float* __restrict__ bias, float* __restrict__ C,
                    int M, int Nout, int K)
{
    __shared__ __align__(16) float As[2][8][64];
    __shared__ __align__(16) float Bs[2][8][128];
    const int tid = threadIdx.x;
    const int tx = tid & 15;
    const int ty = tid >> 4;
    const int m0 = blockIdx.y * 64, n0 = blockIdx.x * 128;

    const int arow = tid >> 1, acol = (tid & 1) * 4;   // A loaders: tid<128 only
    const int brow = tid >> 1, bcol = (tid & 1) * 4;   // B loaders: all 256

    unsigned long long acc[4][4];
    #pragma unroll
    for (int i = 0; i < 4; i++)
        #pragma unroll
        for (int j = 0; j < 4; j++) acc[i][j] = 0ull;

    const int KT = K >> 3;
    float4 ar, br;

    // prologue: load k-tile 0
    if (tid < 128) ar = *(const float4*)&A[(m0 + arow) * K + acol];
    br = *(const float4*)&W[(n0 + brow) * K + bcol];
    if (tid < 128) {
        As[0][acol + 0][arow] = ar.x; As[0][acol + 1][arow] = ar.y;
        As[0][acol + 2][arow] = ar.z; As[0][acol + 3][arow] = ar.w;
    }
    Bs[0][bcol + 0][brow] = br.x; Bs[0][bcol + 1][brow] = br.y;
    Bs[0][bcol + 2][brow] = br.z; Bs[0][bcol + 3][brow] = br.w;
    __syncthreads();

    for (int kt = 0; kt < KT; kt++) {
        const int cur = kt & 1;
        if (kt + 1 < KT) {
            int k0 = (kt + 1) * 8;
            if (tid < 128) ar = *(const float4*)&A[(m0 + arow) * K + k0 + acol];
            br = *(const float4*)&W[(n0 + brow) * K + k0 + bcol];
        }

        const float (*Ac)[64]  = As[cur];
        const float (*Bc)[128] = Bs[cur];
        #pragma unroll
        for (int kk = 0; kk < 8; kk++) {
            float4 av = *(const float4*)&Ac[kk][ty * 4];
            ulonglong2 bp0 = *(const ulonglong2*)&Bc[kk][tx * 4];
            ulonglong2 bp1 = *(const ulonglong2*)&Bc[kk][64 + tx * 4];
            unsigned long long ad0 = pack2(av.x, av.x);
            unsigned long long ad1 = pack2(av.y, av.y);
            unsigned long long ad2 = pack2(av.z, av.z);
            unsigned long long ad3 = pack2(av.w, av.w);
            ffma2(acc[0][0], ad0, bp0.x); ffma2(acc[0][1], ad0, bp0.y);
            ffma2(acc[0][2], ad0, bp1.x); ffma2(acc[0][3], ad0, bp1.y);
            ffma2(acc[1][0], ad1, bp0.x); ffma2(acc[1][1], ad1, bp0.y);
            ffma2(acc[1][2], ad1, bp1.x); ffma2(acc[1][3], ad1, bp1.y);
            ffma2(acc[2][0], ad2, bp0.x); ffma2(acc[2][1], ad2, bp0.y);
            ffma2(acc[2][2], ad2, bp1.x); ffma2(acc[2][3], ad2, bp1.y);
            ffma2(acc[3][0], ad3, bp0.x); ffma2(acc[3][1], ad3, bp0.y);
            ffma2(acc[3][2], ad3, bp1.x); ffma2(acc[3][3], ad3, bp1.y);
        }

        if (kt + 1 < KT) {
            const int nxt = cur ^ 1;
            if (tid < 128) {
                As[nxt][acol + 0][arow] = ar.x; As[nxt][acol + 1][arow] = ar.y;
                As[nxt][acol + 2][arow] = ar.z; As[nxt][acol + 3][arow] = ar.w;
            }
            Bs[nxt][bcol + 0][brow] = br.x; Bs[nxt][bcol + 1][brow] = br.y;
            Bs[nxt][bcol + 2][brow] = br.z; Bs[nxt][bcol + 3][brow] = br.w;
        }
        __syncthreads();
    }

    const int nA = n0 + tx * 4;
    const float4 bia0 = *(const float4*)&bias[nA];
    const float4 bia1 = *(const float4*)&bias[nA + 64];
    #pragma unroll
    for (int i = 0; i < 4; i++) {
        int m = m0 + ty * 4 + i;
        float c0, c1, c2, c3, c4, c5, c6, c7;
        unpack2(acc[i][0], c0, c1); unpack2(acc[i][1], c2, c3);
        unpack2(acc[i][2], c4, c5); unpack2(acc[i][3], c6, c7);
        float4 r0, r1;
        r0.x = c0 + bia0.x; r0.y = c1 + bia0.y; r0.z = c2 + bia0.z; r0.w = c3 + bia0.w;
        r1.x = c4 + bia1.x; r1.y = c5 + bia1.y; r1.z = c6 + bia1.z; r1.w = c7 + bia1.w;
        if (ACT == 1) {
            r0.x = act_elu(r0.x); r0.y = act_elu(r0.y); r0.z = act_elu(r0.z); r0.w = act_elu(r0.w);
            r1.x = act_elu(r1.x); r1.y = act_elu(r1.y); r1.z = act_elu(r1.z); r1.w = act_elu(r1.w);
        }
        if (ACT == 2) {
            r0.x = act_gelu_tanh(r0.x); r0.y = act_gelu_tanh(r0.y);
            r0.z = act_gelu_tanh(r0.z); r0.w = act_gelu_tanh(r0.w);
            r1.x = act_gelu_tanh(r1.x); r1.y = act_gelu_tanh(r1.y);
            r1.z = act_gelu_tanh(r1.z); r1.w = act_gelu_tanh(r1.w);
        }
        *(float4*)&C[m * Nout + nA] = r0;
        *(float4*)&C[m * Nout + nA + 64] = r1;
    }
}

// ---------------- small fallback SGEMM (used for the N=5 head only) ----------------
template <int ACT>
__global__ __launch_bounds__(256)
void gemm_kernel(const float* __restrict__ A, const float* __restrict__ W,
                 const float* __restrict__ bias, float* __restrict__ C,
                 int M, int Nout, int K)
{
    __shared__ float As[16][64];
    __shared__ float Bs[16][64];
    const int tid = threadIdx.x;
    const int tx = tid & 15, ty = tid >> 4;
    const int m0 = blockIdx.y * 64, n0 = blockIdx.x * 64;

    float acc[4][4] = {};

    for (int k0 = 0; k0 < K; k0 += 16) {
        #pragma unroll
        for (int i = tid; i < 1024; i += 256) {
            int r = i >> 4, kk = i & 15;
            int k = k0 + kk;
            As[kk][r] = (k < K) ? A[(m0 + r) * K + k] : 0.f;
            int n = n0 + r;
            Bs[kk][r] = (n < Nout && k < K) ? W[n * K + k] : 0.f;
        }
        __syncthreads();
        #pragma unroll
        for (int kk = 0; kk < 16; kk++) {
            float4 a = *(const float4*)&As[kk][ty * 4];
            float4 b = *(const float4*)&Bs[kk][tx * 4];
            float av[4] = {a.x, a.y, a.z, a.w};
            float bv[4] = {b.x, b.y, b.z, b.w};
            #pragma unroll
            for (int i = 0; i < 4; i++)
                #pragma unroll
                for (int j = 0; j < 4; j++)
                    acc[i][j] += av[i] * bv[j];
        }
        __syncthreads();
    }

    #pragma unroll
    for (int i = 0; i < 4; i++) {
        int m = m0 + ty * 4 + i;
        #pragma unroll
        for (int j = 0; j < 4; j++) {
            int n = n0 + tx * 4 + j;
            if (n < Nout) {
                float v = acc[i][j] + bias[n];
                if (ACT == 1) v = act_elu(v);
                if (ACT == 2) v = act_gelu_tanh(v);
                C[m * Nout + n] = v;
            }
        }
    }
}

// ---------------- GIN pre-init: pre = (1+eps)*x ----------------
__global__ __launch_bounds__(256)
void gin_init_kernel(const float* __restrict__ x, const float* __restrict__ gin_eps,
                     int l, float* __restrict__ pre)
{
    int i = (blockIdx.x * blockDim.x + threadIdx.x) * 4;
    float s = 1.f + gin_eps[l];
    float4 xv = *(const float4*)&x[i];
    float4 r;
    r.x = s * xv.x; r.y = s * xv.y; r.z = s * xv.z; r.w = s * xv.w;
    *(float4*)&pre[i] = r;
}

// ---------------- GIN edge aggregation: pre[dst] += x[src] (edge_index int32) ----------------
__global__ __launch_bounds__(256)
void gin_agg_kernel(const int* __restrict__ ei,
                    const float* __restrict__ x, float* __restrict__ pre)
{
    long long gid = (long long)blockIdx.x * blockDim.x + threadIdx.x;
    int e = (int)(gid >> 6);
    int c = ((int)gid & 63) * 4;
    if (e >= EE) return;
    int src = ei[e];
    int dst = ei[EE + e];
    float4 v = *(const float4*)&x[src * DD + c];
    float* a = &pre[dst * DD + c];
    atomicAdd(a + 0, v.x);
    atomicAdd(a + 1, v.y);
    atomicAdd(a + 2, v.z);
    atomicAdd(a + 3, v.w);
}

// ---------------- fused LayerNorm (+opt ELU) + residual: x += act(LN(in)) ----------------
template <int ACT>
__global__ __launch_bounds__(256)
void ln_res_kernel(const float* __restrict__ in, const float* __restrict__ g,
                   const float* __restrict__ b, float* __restrict__ x)
{
    __shared__ float red[256];
    int row = blockIdx.x, tid = threadIdx.x;
    float v = in[row * DD + tid];

    red[tid] = v;
    __syncthreads();
    #pragma unroll
    for (int s = 128; s > 0; s >>= 1) {
        if (tid < s) red[tid] += red[tid + s];
        __syncthreads();
    }
    float mu = red[0] * (1.f / DD);
    __syncthreads();

    float d = v - mu;
    red[tid] = d * d;
    __syncthreads();
    #pragma unroll
    for (int s = 128; s > 0; s >>= 1) {
        if (tid < s) red[tid] += red[tid + s];
        __syncthreads();
    }
    float var = red[0] * (1.f / DD);

    float y = d * rsqrtf(var + 1e-5f) * g[tid] + b[tid];
    if (ACT == 1) y = act_elu(y);
    x[row * DD + tid] += y;
}

// ---------------- flash attention (fp32, online softmax, f32x2 inner loops) ----------------
__global__ __launch_bounds__(256)
void flash_kernel(const float* __restrict__ qkv, float* __restrict__ out)
{
    __shared__ __align__(16) float Ks[64][36];   // 144B pitch (16B-aligned rows)
    __shared__ __align__(16) float Vs[64][36];
    __shared__ float Ss[64][65];

    const int tid = threadIdx.x;
    const int hh = blockIdx.y;
    const int q0 = blockIdx.x * 64;
    const int row = tid >> 2;
    const int lane4 = tid & 3;
    const int d0 = lane4 * 8;
    const float scale = 0.17677669529663689f;  // 1/sqrt(32)

    // Q row as 16 packed pairs (4x redundant across lane quad; one-time cost)
    unsigned long long qp[16];
    {
        const float* qptr = &qkv[(q0 + row) * 768 + hh * 32];
        #pragma unroll
        for (int p4 = 0; p4 < 8; p4++) {
            ulonglong2 qv = *(const ulonglong2*)&qptr[p4 * 4];
            qp[p4 * 2] = qv.x;
            qp[p4 * 2 + 1] = qv.y;
        }
    }

    float m = -1e30f, l = 0.f;
    unsigned long long o2[4] = {0ull, 0ull, 0ull, 0ull};

    for (int t0 = 0; t0 < NN; t0 += 64) {
        __syncthreads();  // protects Ks/Vs/Ss reuse across iterations
        #pragma unroll
        for (int i = tid; i < 512; i += 256) {
            int r = i >> 3, d = (i & 7) * 4;
            *(float4*)&Ks[r][d] = *(const float4*)&qkv[(t0 + r) * 768 + 256 + hh * 32 + d];
            *(float4*)&Vs[r][d] = *(const float4*)&qkv[(t0 + r) * 768 + 512 + hh * 32 + d];
        }
        __syncthreads();

        // S strip (interleaved rows lane4 + 4j) + running max
        float smax = -1e30f;
        #pragma unroll 4
        for (int j = 0; j < 16; j++) {
            const int kj = lane4 + 4 * j;
            const float* kr = Ks[kj];
            unsigned long long s2 = 0ull;
            #pragma unroll
            for (int p4 = 0; p4 < 8; p4++) {
                ulonglong2 kp = *(const ulonglong2*)&kr[p4 * 4];
                ffma2(s2, qp[p4 * 2], kp.x);
                ffma2(s2, qp[p4 * 2 + 1], kp.y);
            }
            float slo, shi;
            unpack2(s2, slo, shi);
            float s = (slo + shi) * scale;
            Ss[row][kj] = s;
            smax = fmaxf(smax, s);
        }
        smax = fmaxf(smax, __shfl_xor_sync(0xffffffffu, smax, 1));
        smax = fmaxf(smax, __shfl_xor_sync(0xffffffffu, smax, 2));

        float newm = fmaxf(m, smax);
        float alpha = __expf(m - newm);

        float psum = 0.f;
        #pragma unroll 4
        for (int j = 0; j < 16; j++) {
            const int kj = lane4 + 4 * j;
            float p = __expf(Ss[row][kj] - newm);
            Ss[row][kj] = p;
            psum += p;
        }
        psum += __shfl_xor_sync(0xffffffffu, psum, 1);
        psum += __shfl_xor_sync(0xffffffffu, psum, 2);

        l = l * alpha + psum;
        m = newm;

        {
            unsigned long long a2 = pack2(alpha, alpha);
            fmul2(o2[0], o2[0], a2); fmul2(o2[1], o2[1], a2);
            fmul2(o2[2], o2[2], a2); fmul2(o2[3], o2[3], a2);
        }

        __syncwarp();  // quad's Ss writes visible before cross-lane reads

        #pragma unroll 8
        for (int j = 0; j < 64; j++) {
            unsigned long long p2 = pack2(Ss[row][j], Ss[row][j]);
            ulonglong2 v0 = *(const ulonglong2*)&Vs[j][d0];
            ulonglong2 v1 = *(const ulonglong2*)&Vs[j][d0 + 4];
            ffma2(o2[0], p2, v0.x); ffma2(o2[1], p2, v0.y);
            ffma2(o2[2], p2, v1.x); ffma2(o2[3], p2, v1.y);
        }
    }

    float inv = 1.f / l;
    float o[8];
    unpack2(o2[0], o[0], o[1]); unpack2(o2[1], o[2], o[3]);
    unpack2(o2[2], o[4], o[5]); unpack2(o2[3], o[6], o[7]);
    float4 w0, w1;
    w0.x = o[0] * inv; w0.y = o[1] * inv; w0.z = o[2] * inv; w0.w = o[3] * inv;
    w1.x = o[4] * inv; w1.y = o[5] * inv; w1.z = o[6] * inv; w1.w = o[7] * inv;
    float* obase = &out[(q0 + row) * DD + hh * 32 + d0];
    *(float4*)&obase[0] = w0;
    *(float4*)&obase[4] = w1;
}

// ---------------- host orchestration ----------------
extern "C" void kernel_launch(void* const* d_in, const int* in_sizes, int n_in,
                              void* d_out, int out_size)
{
    const float*     x         = (const float*)d_in[0];
    const int*       ei        = (const int*)d_in[1];
    const float*     in_w      = (const float*)d_in[2];
    const float*     in_b      = (const float*)d_in[3];
    const float*     head_w1   = (const float*)d_in[4];
    const float*     head_b1   = (const float*)d_in[5];
    const float*     head_w2   = (const float*)d_in[6];
    const float*     head_b2   = (const float*)d_in[7];
    const float*     mlp_w1    = (const float*)d_in[8];
    const float*     mlp_b1    = (const float*)d_in[9];
    const float*     mlp_w2    = (const float*)d_in[10];
    const float*     mlp_b2    = (const float*)d_in[11];
    const float*     gin_eps   = (const float*)d_in[12];
    const float*     ln1_g     = (const float*)d_in[13];
    const float*     ln1_b     = (const float*)d_in[14];
    const float*     attn_in_w = (const float*)d_in[15];
    const float*     attn_in_b = (const float*)d_in[16];
    const float*     attn_out_w= (const float*)d_in[17];
    const float*     attn_out_b= (const float*)d_in[18];
    const float*     ln2_g     = (const float*)d_in[19];
    const float*     ln2_b     = (const float*)d_in[20];
    const float*     ffn_w1    = (const float*)d_in[21];
    const float*     ffn_b1    = (const float*)d_in[22];
    const float*     ffn_w2    = (const float*)d_in[23];
    const float*     ffn_b2    = (const float*)d_in[24];
    const float*     ln3_g     = (const float*)d_in[25];
    const float*     ln3_b     = (const float*)d_in[26];

    float *h, *pre, *t, *t2, *ao, *emb;
    cudaGetSymbolAddress((void**)&h,   g_h);
    cudaGetSymbolAddress((void**)&pre, g_pre);
    cudaGetSymbolAddress((void**)&t,   g_t);
    cudaGetSymbolAddress((void**)&t2,  g_t2);
    cudaGetSymbolAddress((void**)&ao,  g_ao);
    cudaGetSymbolAddress((void**)&emb, g_emb);

    // input proj + ELU: [4096,72] -> [4096,256]
    gemm_f2_kernel<1><<<dim3(DD / 128, NN / 64), 256>>>(x, in_w, in_b, h, NN, DD, DIN);

    for (int l = 0; l < 2; l++) {
        // ---- GIN ----
        gin_init_kernel<<<(NN * DD / 4) / 256, 256>>>(h, gin_eps, l, pre);
        gin_agg_kernel<<<(EE * 64) / 256, 256>>>(ei, h, pre);
        gemm_f2_kernel<1><<<dim3(DD / 128, NN / 64), 256>>>(
            pre, mlp_w1 + (size_t)l * DD * DD, mlp_b1 + (size_t)l * DD, t, NN, DD, DD);
        gemm_f2_kernel<0><<<dim3(DD / 128, NN / 64), 256>>>(
            t, mlp_w2 + (size_t)l * DD * DD, mlp_b2 + (size_t)l * DD, t2, NN, DD, DD);
        ln_res_kernel<1><<<NN, 256>>>(t2, ln1_g + (size_t)l * DD, ln1_b + (size_t)l * DD, h);

        // ---- global attention ----
        gemm_f2_kernel<0><<<dim3(768 / 128, NN / 64), 256>>>(
            h, attn_in_w + (size_t)l * 768 * DD, attn_in_b + (size_t)l * 768, t, NN, 768, DD);
        flash_kernel<<<dim3(NN / 64, HH), 256>>>(t, ao);
        gemm_f2_kernel<0><<<dim3(DD / 128, NN / 64), 256>>>(
            ao, attn_out_w + (size_t)l * DD * DD, attn_out_b + (size_t)l * DD, t2, NN, DD, DD);
        ln_res_kernel<0><<<NN, 256>>>(t2, ln2_g + (size_t)l * DD, ln2_b + (size_t)l * DD, h);

        // ---- FFN ----
        gemm_f2_kernel<2><<<dim3(512 / 128, NN / 64), 256>>>(
            h, ffn_w1 + (size_t)l * 512 * DD, ffn_b1 + (size_t)l * 512, t, NN, 512, DD);
        gemm_f2_kernel<0><<<dim3(DD / 128, NN / 64), 256>>>(
            t, ffn_w2 + (size_t)l * DD * 512, ffn_b2 + (size_t)l * DD, t2, NN, DD, 512);
        ln_res_kernel<0><<<NN, 256>>>(t2, ln3_g + (size_t)l * DD, ln3_b + (size_t)l * DD, h);
    }

    // ---- head ----
    gemm_f2_kernel<1><<<dim3(DEMB / 128, NN / 64), 256>>>(h, head_w1, head_b1, emb, NN, DEMB, DD);
    gemm_kernel<0><<<dim3(1, NN / 64), 256>>>(emb, head_w2, head_b2, (float*)d_out, NN, TT, DEMB);
}

// round 7
// speedup vs baseline: 1.6184x; 1.4768x over previous
#include <cuda_runtime.h>
#include <cuda_bf16.h>
#include <math.h>

#define NN 4096
#define EE 131072
#define DIN 72
#define DD 256
#define HH 8
#define HDD 32
#define DEMB 128
#define TT 5

// ---------------- scratch (device globals; no runtime allocation) ----------------
__device__ float g_h  [NN * DD];
__device__ float g_pre[NN * DD];
__device__ float g_t  [NN * 768];
__device__ float g_t2 [NN * DD];
__device__ float g_ao [NN * DD];
__device__ float g_emb[NN * DEMB];

// ---------------- f32x2 packed helpers (exact fp32 semantics, 2 FMA / inst) ----------------
__device__ __forceinline__ unsigned long long pack2(float lo, float hi) {
    unsigned long long r;
    asm("mov.b64 %0, {%1, %2};" : "=l"(r) : "f"(lo), "f"(hi));
    return r;
}
__device__ __forceinline__ void unpack2(unsigned long long v, float& lo, float& hi) {
    asm("mov.b64 {%0, %1}, %2;" : "=f"(lo), "=f"(hi) : "l"(v));
}
__device__ __forceinline__ void ffma2(unsigned long long& d, unsigned long long a,
                                      unsigned long long b) {
    asm("fma.rn.f32x2 %0, %1, %2, %0;" : "+l"(d) : "l"(a), "l"(b));
}
__device__ __forceinline__ void fmul2(unsigned long long& d, unsigned long long a,
                                      unsigned long long b) {
    asm("mul.rn.f32x2 %0, %1, %2;" : "=l"(d) : "l"(a), "l"(b));
}

// ---------------- activations ----------------
__device__ __forceinline__ float act_elu(float v) {
    return v > 0.f ? v : expm1f(v);
}
__device__ __forceinline__ float act_gelu_tanh(float v) {
    const float c = 0.7978845608028654f;   // sqrt(2/pi)
    float u = c * (v + 0.044715f * v * v * v);
    return 0.5f * v * (1.f + tanhf(u));
}

// ---------------- f32x2 SGEMM, BN=128: C = act(A @ W^T + b) ----------------
// BM=64, BN=128, BK=8, 256 threads. Requires M%64==0, Nout%128==0, K%8==0.
template <int ACT>
__global__ __launch_bounds__(256)
void gemm_f2_kernel(const float* __restrict__ A, const float* __restrict__ W,
                    const float* __restrict__ bias, float* __restrict__ C,
                    int M, int Nout, int K)
{
    __shared__ __align__(16) float As[2][8][64];
    __shared__ __align__(16) float Bs[2][8][128];
    const int tid = threadIdx.x;
    const int tx = tid & 15;
    const int ty = tid >> 4;
    const int m0 = blockIdx.y * 64, n0 = blockIdx.x * 128;

    const int arow = tid >> 1, acol = (tid & 1) * 4;   // A loaders: tid<128
    const int brow = tid >> 1, bcol = (tid & 1) * 4;   // B loaders: all 256

    unsigned long long acc[4][4];
    #pragma unroll
    for (int i = 0; i < 4; i++)
        #pragma unroll
        for (int j = 0; j < 4; j++) acc[i][j] = 0ull;

    const int KT = K >> 3;
    float4 ar, br;

    if (tid < 128) ar = *(const float4*)&A[(m0 + arow) * K + acol];
    br = *(const float4*)&W[(n0 + brow) * K + bcol];
    if (tid < 128) {
        As[0][acol + 0][arow] = ar.x; As[0][acol + 1][arow] = ar.y;
        As[0][acol + 2][arow] = ar.z; As[0][acol + 3][arow] = ar.w;
    }
    Bs[0][bcol + 0][brow] = br.x; Bs[0][bcol + 1][brow] = br.y;
    Bs[0][bcol + 2][brow] = br.z; Bs[0][bcol + 3][brow] = br.w;
    __syncthreads();

    for (int kt = 0; kt < KT; kt++) {
        const int cur = kt & 1;
        if (kt + 1 < KT) {
            int k0 = (kt + 1) * 8;
            if (tid < 128) ar = *(const float4*)&A[(m0 + arow) * K + k0 + acol];
            br = *(const float4*)&W[(n0 + brow) * K + k0 + bcol];
        }

        const float (*Ac)[64]  = As[cur];
        const float (*Bc)[128] = Bs[cur];
        #pragma unroll
        for (int kk = 0; kk < 8; kk++) {
            float4 av = *(const float4*)&Ac[kk][ty * 4];
            ulonglong2 bp0 = *(const ulonglong2*)&Bc[kk][tx * 4];
            ulonglong2 bp1 = *(const ulonglong2*)&Bc[kk][64 + tx * 4];
            unsigned long long ad0 = pack2(av.x, av.x);
            unsigned long long ad1 = pack2(av.y, av.y);
            unsigned long long ad2 = pack2(av.z, av.z);
            unsigned long long ad3 = pack2(av.w, av.w);
            ffma2(acc[0][0], ad0, bp0.x); ffma2(acc[0][1], ad0, bp0.y);
            ffma2(acc[0][2], ad0, bp1.x); ffma2(acc[0][3], ad0, bp1.y);
            ffma2(acc[1][0], ad1, bp0.x); ffma2(acc[1][1], ad1, bp0.y);
            ffma2(acc[1][2], ad1, bp1.x); ffma2(acc[1][3], ad1, bp1.y);
            ffma2(acc[2][0], ad2, bp0.x); ffma2(acc[2][1], ad2, bp0.y);
            ffma2(acc[2][2], ad2, bp1.x); ffma2(acc[2][3], ad2, bp1.y);
            ffma2(acc[3][0], ad3, bp0.x); ffma2(acc[3][1], ad3, bp0.y);
            ffma2(acc[3][2], ad3, bp1.x); ffma2(acc[3][3], ad3, bp1.y);
        }

        if (kt + 1 < KT) {
            const int nxt = cur ^ 1;
            if (tid < 128) {
                As[nxt][acol + 0][arow] = ar.x; As[nxt][acol + 1][arow] = ar.y;
                As[nxt][acol + 2][arow] = ar.z; As[nxt][acol + 3][arow] = ar.w;
            }
            Bs[nxt][bcol + 0][brow] = br.x; Bs[nxt][bcol + 1][brow] = br.y;
            Bs[nxt][bcol + 2][brow] = br.z; Bs[nxt][bcol + 3][brow] = br.w;
        }
        __syncthreads();
    }

    const int nA = n0 + tx * 4;
    const float4 bia0 = *(const float4*)&bias[nA];
    const float4 bia1 = *(const float4*)&bias[nA + 64];
    #pragma unroll
    for (int i = 0; i < 4; i++) {
        int m = m0 + ty * 4 + i;
        float c0, c1, c2, c3, c4, c5, c6, c7;
        unpack2(acc[i][0], c0, c1); unpack2(acc[i][1], c2, c3);
        unpack2(acc[i][2], c4, c5); unpack2(acc[i][3], c6, c7);
        float4 r0, r1;
        r0.x = c0 + bia0.x; r0.y = c1 + bia0.y; r0.z = c2 + bia0.z; r0.w = c3 + bia0.w;
        r1.x = c4 + bia1.x; r1.y = c5 + bia1.y; r1.z = c6 + bia1.z; r1.w = c7 + bia1.w;
        if (ACT == 1) {
            r0.x = act_elu(r0.x); r0.y = act_elu(r0.y); r0.z = act_elu(r0.z); r0.w = act_elu(r0.w);
            r1.x = act_elu(r1.x); r1.y = act_elu(r1.y); r1.z = act_elu(r1.z); r1.w = act_elu(r1.w);
        }
        if (ACT == 2) {
            r0.x = act_gelu_tanh(r0.x); r0.y = act_gelu_tanh(r0.y);
            r0.z = act_gelu_tanh(r0.z); r0.w = act_gelu_tanh(r0.w);
            r1.x = act_gelu_tanh(r1.x); r1.y = act_gelu_tanh(r1.y);
            r1.z = act_gelu_tanh(r1.z); r1.w = act_gelu_tanh(r1.w);
        }
        *(float4*)&C[m * Nout + nA] = r0;
        *(float4*)&C[m * Nout + nA + 64] = r1;
    }
}

// ---------------- f32x2 SGEMM, BN=64 (2x grid for narrow outputs) ----------------
// BM=64, BN=64, BK=8, 256 threads. Requires M%64==0, Nout%64==0, K%8==0.
template <int ACT>
__global__ __launch_bounds__(256)
void gemm64_kernel(const float* __restrict__ A, const float* __restrict__ W,
                   const float* __restrict__ bias, float* __restrict__ C,
                   int M, int Nout, int K)
{
    __shared__ __align__(16) float As[2][8][64];
    __shared__ __align__(16) float Bs[2][8][64];
    const int tid = threadIdx.x;
    const int tx = tid & 15;
    const int ty = tid >> 4;
    const int m0 = blockIdx.y * 64, n0 = blockIdx.x * 64;

    // loaders: tid<128 -> A, tid>=128 -> B
    const int lrow = (tid & 127) >> 1, lcol = (tid & 1) * 4;

    unsigned long long acc[4][2];
    #pragma unroll
    for (int i = 0; i < 4; i++) { acc[i][0] = 0ull; acc[i][1] = 0ull; }

    const int KT = K >> 3;
    float4 lr;

    if (tid < 128) lr = *(const float4*)&A[(m0 + lrow) * K + lcol];
    else           lr = *(const float4*)&W[(n0 + lrow) * K + lcol];
    {
        float (*dst)[64] = (tid < 128) ? As[0] : Bs[0];
        dst[lcol + 0][lrow] = lr.x; dst[lcol + 1][lrow] = lr.y;
        dst[lcol + 2][lrow] = lr.z; dst[lcol + 3][lrow] = lr.w;
    }
    __syncthreads();

    for (int kt = 0; kt < KT; kt++) {
        const int cur = kt & 1;
        if (kt + 1 < KT) {
            int k0 = (kt + 1) * 8;
            if (tid < 128) lr = *(const float4*)&A[(m0 + lrow) * K + k0 + lcol];
            else           lr = *(const float4*)&W[(n0 + lrow) * K + k0 + lcol];
        }

        const float (*Ac)[64] = As[cur];
        const float (*Bc)[64] = Bs[cur];
        #pragma unroll
        for (int kk = 0; kk < 8; kk++) {
            float4 av = *(const float4*)&Ac[kk][ty * 4];
            ulonglong2 bp = *(const ulonglong2*)&Bc[kk][tx * 4];
            unsigned long long ad0 = pack2(av.x, av.x);
            unsigned long long ad1 = pack2(av.y, av.y);
            unsigned long long ad2 = pack2(av.z, av.z);
            unsigned long long ad3 = pack2(av.w, av.w);
            ffma2(acc[0][0], ad0, bp.x); ffma2(acc[0][1], ad0, bp.y);
            ffma2(acc[1][0], ad1, bp.x); ffma2(acc[1][1], ad1, bp.y);
            ffma2(acc[2][0], ad2, bp.x); ffma2(acc[2][1], ad2, bp.y);
            ffma2(acc[3][0], ad3, bp.x); ffma2(acc[3][1], ad3, bp.y);
        }

        if (kt + 1 < KT) {
            float (*dst)[64] = (tid < 128) ? As[cur ^ 1] : Bs[cur ^ 1];
            dst[lcol + 0][lrow] = lr.x; dst[lcol + 1][lrow] = lr.y;
            dst[lcol + 2][lrow] = lr.z; dst[lcol + 3][lrow] = lr.w;
        }
        __syncthreads();
    }

    const int nA = n0 + tx * 4;
    const float4 bia = *(const float4*)&bias[nA];
    #pragma unroll
    for (int i = 0; i < 4; i++) {
        int m = m0 + ty * 4 + i;
        float c0, c1, c2, c3;
        unpack2(acc[i][0], c0, c1); unpack2(acc[i][1], c2, c3);
        float4 r0;
        r0.x = c0 + bia.x; r0.y = c1 + bia.y; r0.z = c2 + bia.z; r0.w = c3 + bia.w;
        if (ACT == 1) {
            r0.x = act_elu(r0.x); r0.y = act_elu(r0.y);
            r0.z = act_elu(r0.z); r0.w = act_elu(r0.w);
        }
        if (ACT == 2) {
            r0.x = act_gelu_tanh(r0.x); r0.y = act_gelu_tanh(r0.y);
            r0.z = act_gelu_tanh(r0.z); r0.w = act_gelu_tanh(r0.w);
        }
        *(float4*)&C[m * Nout + nA] = r0;
    }
}

// ---------------- small fallback SGEMM (N=5 head only) ----------------
template <int ACT>
__global__ __launch_bounds__(256)
void gemm_kernel(const float* __restrict__ A, const float* __restrict__ W,
                 const float* __restrict__ bias, float* __restrict__ C,
                 int M, int Nout, int K)
{
    __shared__ float As[16][64];
    __shared__ float Bs[16][64];
    const int tid = threadIdx.x;
    const int tx = tid & 15, ty = tid >> 4;
    const int m0 = blockIdx.y * 64, n0 = blockIdx.x * 64;

    float acc[4][4] = {};

    for (int k0 = 0; k0 < K; k0 += 16) {
        #pragma unroll
        for (int i = tid; i < 1024; i += 256) {
            int r = i >> 4, kk = i & 15;
            int k = k0 + kk;
            As[kk][r] = (k < K) ? A[(m0 + r) * K + k] : 0.f;
            int n = n0 + r;
            Bs[kk][r] = (n < Nout && k < K) ? W[n * K + k] : 0.f;
        }
        __syncthreads();
        #pragma unroll
        for (int kk = 0; kk < 16; kk++) {
            float4 a = *(const float4*)&As[kk][ty * 4];
            float4 b = *(const float4*)&Bs[kk][tx * 4];
            float av[4] = {a.x, a.y, a.z, a.w};
            float bv[4] = {b.x, b.y, b.z, b.w};
            #pragma unroll
            for (int i = 0; i < 4; i++)
                #pragma unroll
                for (int j = 0; j < 4; j++)
                    acc[i][j] += av[i] * bv[j];
        }
        __syncthreads();
    }

    #pragma unroll
    for (int i = 0; i < 4; i++) {
        int m = m0 + ty * 4 + i;
        #pragma unroll
        for (int j = 0; j < 4; j++) {
            int n = n0 + tx * 4 + j;
            if (n < Nout) {
                float v = acc[i][j] + bias[n];
                if (ACT == 1) v = act_elu(v);
                if (ACT == 2) v = act_gelu_tanh(v);
                C[m * Nout + n] = v;
            }
        }
    }
}

// ---------------- GIN pre-init: pre = (1+eps)*x ----------------
__global__ __launch_bounds__(256)
void gin_init_kernel(const float* __restrict__ x, const float* __restrict__ gin_eps,
                     int l, float* __restrict__ pre)
{
    int i = (blockIdx.x * blockDim.x + threadIdx.x) * 4;
    float s = 1.f + gin_eps[l];
    float4 xv = *(const float4*)&x[i];
    float4 r;
    r.x = s * xv.x; r.y = s * xv.y; r.z = s * xv.z; r.w = s * xv.w;
    *(float4*)&pre[i] = r;
}

// ---------------- GIN edge aggregation: pre[dst] += x[src] (edge_index int32) ----------------
__global__ __launch_bounds__(256)
void gin_agg_kernel(const int* __restrict__ ei,
                    const float* __restrict__ x, float* __restrict__ pre)
{
    long long gid = (long long)blockIdx.x * blockDim.x + threadIdx.x;
    int e = (int)(gid >> 6);
    int c = ((int)gid & 63) * 4;
    if (e >= EE) return;
    int src = ei[e];
    int dst = ei[EE + e];
    float4 v = *(const float4*)&x[src * DD + c];
    float* a = &pre[dst * DD + c];
    atomicAdd(a + 0, v.x);
    atomicAdd(a + 1, v.y);
    atomicAdd(a + 2, v.z);
    atomicAdd(a + 3, v.w);
}

// ---------------- fused LayerNorm (+opt ELU) + residual ----------------
template <int ACT>
__global__ __launch_bounds__(256)
void ln_res_kernel(const float* __restrict__ in, const float* __restrict__ g,
                   const float* __restrict__ b, float* __restrict__ x)
{
    __shared__ float red[256];
    int row = blockIdx.x, tid = threadIdx.x;
    float v = in[row * DD + tid];

    red[tid] = v;
    __syncthreads();
    #pragma unroll
    for (int s = 128; s > 0; s >>= 1) {
        if (tid < s) red[tid] += red[tid + s];
        __syncthreads();
    }
    float mu = red[0] * (1.f / DD);
    __syncthreads();

    float d = v - mu;
    red[tid] = d * d;
    __syncthreads();
    #pragma unroll
    for (int s = 128; s > 0; s >>= 1) {
        if (tid < s) red[tid] += red[tid + s];
        __syncthreads();
    }
    float var = red[0] * (1.f / DD);

    float y = d * rsqrtf(var + 1e-5f) * g[tid] + b[tid];
    if (ACT == 1) y = act_elu(y);
    x[row * DD + tid] += y;
}

// ---------------- flash attention: 2 query rows / thread, f32x2 ----------------
// Block = 256 threads handles 128 q-rows (row, row+64). grid = (N/128, H).
// Dynamic smem: Ks[64][36] | Vs[64][36] | Ss[128][65]  (50.5 KB).
__global__ __launch_bounds__(256)
void flash2_kernel(const float* __restrict__ qkv, float* __restrict__ out)
{
    extern __shared__ __align__(16) float sm[];
    float (*Ks)[36] = (float(*)[36])sm;
    float (*Vs)[36] = (float(*)[36])(sm + 64 * 36);
    float (*Ss)[65] = (float(*)[65])(sm + 2 * 64 * 36);

    const int tid = threadIdx.x;
    const int hh = blockIdx.y;
    const int q0 = blockIdx.x * 128;
    const int row = tid >> 2;          // 0..63
    const int lane4 = tid & 3;
    const int d0 = lane4 * 8;
    const float scale = 0.17677669529663689f;  // 1/sqrt(32)

    const int ra = q0 + row;
    const int rb = ra + 64;

    // Q rows (scale folded), packed as f32x2 pairs
    unsigned long long qa[16], qb[16];
    {
        const float* pa = &qkv[ra * 768 + hh * 32];
        const float* pb = &qkv[rb * 768 + hh * 32];
        #pragma unroll
        for (int p4 = 0; p4 < 8; p4++) {
            float4 va = *(const float4*)&pa[p4 * 4];
            float4 vb = *(const float4*)&pb[p4 * 4];
            qa[p4 * 2]     = pack2(va.x * scale, va.y * scale);
            qa[p4 * 2 + 1] = pack2(va.z * scale, va.w * scale);
            qb[p4 * 2]     = pack2(vb.x * scale, vb.y * scale);
            qb[p4 * 2 + 1] = pack2(vb.z * scale, vb.w * scale);
        }
    }

    float ma = -1e30f, la = 0.f, mb = -1e30f, lb = 0.f;
    unsigned long long oa[4] = {0ull, 0ull, 0ull, 0ull};
    unsigned long long ob[4] = {0ull, 0ull, 0ull, 0ull};

    for (int t0 = 0; t0 < NN; t0 += 64) {
        __syncthreads();   // Ks/Vs/Ss reuse guard
        #pragma unroll
        for (int i = tid; i < 512; i += 256) {
            int r = i >> 3, d = (i & 7) * 4;
            *(float4*)&Ks[r][d] = *(const float4*)&qkv[(t0 + r) * 768 + 256 + hh * 32 + d];
            *(float4*)&Vs[r][d] = *(const float4*)&qkv[(t0 + r) * 768 + 512 + hh * 32 + d];
        }
        __syncthreads();

        // QK for both rows over this lane's 16-key interleaved strip
        float smaxa = -1e30f, smaxb = -1e30f;
        #pragma unroll 4
        for (int j = 0; j < 16; j++) {
            const int kj = lane4 + 4 * j;
            const float* kr = Ks[kj];
            unsigned long long s2a = 0ull, s2b = 0ull;
            #pragma unroll
            for (int p4 = 0; p4 < 8; p4++) {
                ulonglong2 kp = *(const ulonglong2*)&kr[p4 * 4];
                ffma2(s2a, qa[p4 * 2], kp.x);
                ffma2(s2a, qa[p4 * 2 + 1], kp.y);
                ffma2(s2b, qb[p4 * 2], kp.x);
                ffma2(s2b, qb[p4 * 2 + 1], kp.y);
            }
            float xlo, xhi, ylo, yhi;
            unpack2(s2a, xlo, xhi);
            unpack2(s2b, ylo, yhi);
            float sa = xlo + xhi, sb = ylo + yhi;
            Ss[row][kj] = sa;
            Ss[row + 64][kj] = sb;
            smaxa = fmaxf(smaxa, sa);
            smaxb = fmaxf(smaxb, sb);
        }
        smaxa = fmaxf(smaxa, __shfl_xor_sync(0xffffffffu, smaxa, 1));
        smaxa = fmaxf(smaxa, __shfl_xor_sync(0xffffffffu, smaxa, 2));
        smaxb = fmaxf(smaxb, __shfl_xor_sync(0xffffffffu, smaxb, 1));
        smaxb = fmaxf(smaxb, __shfl_xor_sync(0xffffffffu, smaxb, 2));

        float newma = fmaxf(ma, smaxa), alphaa = __expf(ma - newma);
        float newmb = fmaxf(mb, smaxb), alphab = __expf(mb - newmb);

        float psa = 0.f, psb = 0.f;
        #pragma unroll 4
        for (int j = 0; j < 16; j++) {
            const int kj = lane4 + 4 * j;
            float pa_ = __expf(Ss[row][kj] - newma);
            float pb_ = __expf(Ss[row + 64][kj] - newmb);
            Ss[row][kj] = pa_;
            Ss[row + 64][kj] = pb_;
            psa += pa_;
            psb += pb_;
        }
        psa += __shfl_xor_sync(0xffffffffu, psa, 1);
        psa += __shfl_xor_sync(0xffffffffu, psa, 2);
        psb += __shfl_xor_sync(0xffffffffu, psb, 1);
        psb += __shfl_xor_sync(0xffffffffu, psb, 2);

        la = la * alphaa + psa; ma = newma;
        lb = lb * alphab + psb; mb = newmb;

        {
            unsigned long long a2 = pack2(alphaa, alphaa);
            unsigned long long b2 = pack2(alphab, alphab);
            fmul2(oa[0], oa[0], a2); fmul2(oa[1], oa[1], a2);
            fmul2(oa[2], oa[2], a2); fmul2(oa[3], oa[3], a2);
            fmul2(ob[0], ob[0], b2); fmul2(ob[1], ob[1], b2);
            fmul2(ob[2], ob[2], b2); fmul2(ob[3], ob[3], b2);
        }

        __syncwarp();   // quad's Ss writes visible before cross-lane reads

        #pragma unroll 4
        for (int j = 0; j < 64; j++) {
            unsigned long long p2a = pack2(Ss[row][j], Ss[row][j]);
            unsigned long long p2b = pack2(Ss[row + 64][j], Ss[row + 64][j]);
            ulonglong2 v0 = *(const ulonglong2*)&Vs[j][d0];
            ulonglong2 v1 = *(const ulonglong2*)&Vs[j][d0 + 4];
            ffma2(oa[0], p2a, v0.x); ffma2(oa[1], p2a, v0.y);
            ffma2(oa[2], p2a, v1.x); ffma2(oa[3], p2a, v1.y);
            ffma2(ob[0], p2b, v0.x); ffma2(ob[1], p2b, v0.y);
            ffma2(ob[2], p2b, v1.x); ffma2(ob[3], p2b, v1.y);
        }
    }

    {
        float inv = 1.f / la;
        float o[8];
        unpack2(oa[0], o[0], o[1]); unpack2(oa[1], o[2], o[3]);
        unpack2(oa[2], o[4], o[5]); unpack2(oa[3], o[6], o[7]);
        float4 w0, w1;
        w0.x = o[0] * inv; w0.y = o[1] * inv; w0.z = o[2] * inv; w0.w = o[3] * inv;
        w1.x = o[4] * inv; w1.y = o[5] * inv; w1.z = o[6] * inv; w1.w = o[7] * inv;
        float* obase = &out[ra * DD + hh * 32 + d0];
        *(float4*)&obase[0] = w0;
        *(float4*)&obase[4] = w1;
    }
    {
        float inv = 1.f / lb;
        float o[8];
        unpack2(ob[0], o[0], o[1]); unpack2(ob[1], o[2], o[3]);
        unpack2(ob[2], o[4], o[5]); unpack2(ob[3], o[6], o[7]);
        float4 w0, w1;
        w0.x = o[0] * inv; w0.y = o[1] * inv; w0.z = o[2] * inv; w0.w = o[3] * inv;
        w1.x = o[4] * inv; w1.y = o[5] * inv; w1.z = o[6] * inv; w1.w = o[7] * inv;
        float* obase = &out[rb * DD + hh * 32 + d0];
        *(float4*)&obase[0] = w0;
        *(float4*)&obase[4] = w1;
    }
}

// ---------------- host orchestration ----------------
extern "C" void kernel_launch(void* const* d_in, const int* in_sizes, int n_in,
                              void* d_out, int out_size)
{
    const float*     x         = (const float*)d_in[0];
    const int*       ei        = (const int*)d_in[1];
    const float*     in_w      = (const float*)d_in[2];
    const float*     in_b      = (const float*)d_in[3];
    const float*     head_w1   = (const float*)d_in[4];
    const float*     head_b1   = (const float*)d_in[5];
    const float*     head_w2   = (const float*)d_in[6];
    const float*     head_b2   = (const float*)d_in[7];
    const float*     mlp_w1    = (const float*)d_in[8];
    const float*     mlp_b1    = (const float*)d_in[9];
    const float*     mlp_w2    = (const float*)d_in[10];
    const float*     mlp_b2    = (const float*)d_in[11];
    const float*     gin_eps   = (const float*)d_in[12];
    const float*     ln1_g     = (const float*)d_in[13];
    const float*     ln1_b     = (const float*)d_in[14];
    const float*     attn_in_w = (const float*)d_in[15];
    const float*     attn_in_b = (const float*)d_in[16];
    const float*     attn_out_w= (const float*)d_in[17];
    const float*     attn_out_b= (const float*)d_in[18];
    const float*     ln2_g     = (const float*)d_in[19];
    const float*     ln2_b     = (const float*)d_in[20];
    const float*     ffn_w1    = (const float*)d_in[21];
    const float*     ffn_b1    = (const float*)d_in[22];
    const float*     ffn_w2    = (const float*)d_in[23];
    const float*     ffn_b2    = (const float*)d_in[24];
    const float*     ln3_g     = (const float*)d_in[25];
    const float*     ln3_b     = (const float*)d_in[26];

    float *h, *pre, *t, *t2, *ao, *emb;
    cudaGetSymbolAddress((void**)&h,   g_h);
    cudaGetSymbolAddress((void**)&pre, g_pre);
    cudaGetSymbolAddress((void**)&t,   g_t);
    cudaGetSymbolAddress((void**)&t2,  g_t2);
    cudaGetSymbolAddress((void**)&ao,  g_ao);
    cudaGetSymbolAddress((void**)&emb, g_emb);

    const int FLASH_SMEM = (2 * 64 * 36 + 128 * 65) * 4;   // 50944 B
    cudaFuncSetAttribute(flash2_kernel,
                         cudaFuncAttributeMaxDynamicSharedMemorySize, FLASH_SMEM);

    // input proj + ELU
    gemm64_kernel<1><<<dim3(DD / 64, NN / 64), 256>>>(x, in_w, in_b, h, NN, DD, DIN);

    for (int l = 0; l < 2; l++) {
        // ---- GIN ----
        gin_init_kernel<<<(NN * DD / 4) / 256, 256>>>(h, gin_eps, l, pre);
        gin_agg_kernel<<<(EE * 64) / 256, 256>>>(ei, h, pre);
        gemm64_kernel<1><<<dim3(DD / 64, NN / 64), 256>>>(
            pre, mlp_w1 + (size_t)l * DD * DD, mlp_b1 + (size_t)l * DD, t, NN, DD, DD);
        gemm64_kernel<0><<<dim3(DD / 64, NN / 64), 256>>>(
            t, mlp_w2 + (size_t)l * DD * DD, mlp_b2 + (size_t)l * DD, t2, NN, DD, DD);
        ln_res_kernel<1><<<NN, 256>>>(t2, ln1_g + (size_t)l * DD, ln1_b + (size_t)l * DD, h);

        // ---- global attention ----
        gemm_f2_kernel<0><<<dim3(768 / 128, NN / 64), 256>>>(
            h, attn_in_w + (size_t)l * 768 * DD, attn_in_b + (size_t)l * 768, t, NN, 768, DD);
        flash2_kernel<<<dim3(NN / 128, HH), 256, FLASH_SMEM>>>(t, ao);
        gemm64_kernel<0><<<dim3(DD / 64, NN / 64), 256>>>(
            ao, attn_out_w + (size_t)l * DD * DD, attn_out_b + (size_t)l * DD, t2, NN, DD, DD);
        ln_res_kernel<0><<<NN, 256>>>(t2, ln2_g + (size_t)l * DD, ln2_b + (size_t)l * DD, h);

        // ---- FFN ----
        gemm_f2_kernel<2><<<dim3(512 / 128, NN / 64), 256>>>(
            h, ffn_w1 + (size_t)l * 512 * DD, ffn_b1 + (size_t)l * 512, t, NN, 512, DD);
        gemm64_kernel<0><<<dim3(DD / 64, NN / 64), 256>>>(
            t, ffn_w2 + (size_t)l * DD * 512, ffn_b2 + (size_t)l * DD, t2, NN, DD, 512);
        ln_res_kernel<0><<<NN, 256>>>(t2, ln3_g + (size_t)l * DD, ln3_b + (size_t)l * DD, h);
    }

    // ---- head ----
    gemm64_kernel<1><<<dim3(DEMB / 64, NN / 64), 256>>>(h, head_w1, head_b1, emb, NN, DEMB, DD);
    gemm_kernel<0><<<dim3(1, NN / 64), 256>>>(emb, head_w2, head_b2, (float*)d_out, NN, TT, DEMB);
}

// round 8
// speedup vs baseline: 3.0148x; 1.8629x over previous
#include <cuda_runtime.h>
#include <cuda_bf16.h>
#include <math.h>

#define NN 4096
#define EE 131072
#define DIN 72
#define DD 256
#define HH 8
#define HDD 32
#define DEMB 128
#define TT 5

// ---------------- scratch (device globals; no runtime allocation) ----------------
__device__ float g_h  [NN * DD];
__device__ float g_pre[NN * DD];
__device__ float g_t  [NN * 768];
__device__ float g_t2 [NN * DD];
__device__ float g_ao [NN * DD];
__device__ float g_emb[NN * DEMB];

// ---------------- f32x2 packed helpers ----------------
__device__ __forceinline__ unsigned long long pack2(float lo, float hi) {
    unsigned long long r;
    asm("mov.b64 %0, {%1, %2};" : "=l"(r) : "f"(lo), "f"(hi));
    return r;
}
__device__ __forceinline__ void unpack2(unsigned long long v, float& lo, float& hi) {
    asm("mov.b64 {%0, %1}, %2;" : "=f"(lo), "=f"(hi) : "l"(v));
}
__device__ __forceinline__ void ffma2(unsigned long long& d, unsigned long long a,
                                      unsigned long long b) {
    asm("fma.rn.f32x2 %0, %1, %2, %0;" : "+l"(d) : "l"(a), "l"(b));
}

// ---------------- tf32 mma helpers ----------------
__device__ __forceinline__ unsigned cvt_tf32(float x) {
    unsigned r;
    asm("cvt.rna.tf32.f32 %0, %1;" : "=r"(r) : "f"(x));
    return r;
}
__device__ __forceinline__ void mma_tf32(float* c, const unsigned* a,
                                         unsigned b0, unsigned b1) {
    asm volatile(
        "mma.sync.aligned.m16n8k8.row.col.f32.tf32.tf32.f32 "
        "{%0,%1,%2,%3}, {%4,%5,%6,%7}, {%8,%9}, {%0,%1,%2,%3};\n"
        : "+f"(c[0]), "+f"(c[1]), "+f"(c[2]), "+f"(c[3])
        : "r"(a[0]), "r"(a[1]), "r"(a[2]), "r"(a[3]), "r"(b0), "r"(b1));
}

// ---------------- activations ----------------
__device__ __forceinline__ float act_elu(float v) {
    return v > 0.f ? v : expm1f(v);
}
__device__ __forceinline__ float act_gelu_tanh(float v) {
    const float c = 0.7978845608028654f;   // sqrt(2/pi)
    float u = c * (v + 0.044715f * v * v * v);
    return 0.5f * v * (1.f + tanhf(u));
}

// ---------------- f32x2 SGEMM, BN=128 ----------------
template <int ACT>
__global__ __launch_bounds__(256)
void gemm_f2_kernel(const float* __restrict__ A, const float* __restrict__ W,
                    const float* __restrict__ bias, float* __restrict__ C,
                    int M, int Nout, int K)
{
    __shared__ __align__(16) float As[2][8][64];
    __shared__ __align__(16) float Bs[2][8][128];
    const int tid = threadIdx.x;
    const int tx = tid & 15;
    const int ty = tid >> 4;
    const int m0 = blockIdx.y * 64, n0 = blockIdx.x * 128;

    const int arow = tid >> 1, acol = (tid & 1) * 4;
    const int brow = tid >> 1, bcol = (tid & 1) * 4;

    unsigned long long acc[4][4];
    #pragma unroll
    for (int i = 0; i < 4; i++)
        #pragma unroll
        for (int j = 0; j < 4; j++) acc[i][j] = 0ull;

    const int KT = K >> 3;
    float4 ar, br;

    if (tid < 128) ar = *(const float4*)&A[(m0 + arow) * K + acol];
    br = *(const float4*)&W[(n0 + brow) * K + bcol];
    if (tid < 128) {
        As[0][acol + 0][arow] = ar.x; As[0][acol + 1][arow] = ar.y;
        As[0][acol + 2][arow] = ar.z; As[0][acol + 3][arow] = ar.w;
    }
    Bs[0][bcol + 0][brow] = br.x; Bs[0][bcol + 1][brow] = br.y;
    Bs[0][bcol + 2][brow] = br.z; Bs[0][bcol + 3][brow] = br.w;
    __syncthreads();

    for (int kt = 0; kt < KT; kt++) {
        const int cur = kt & 1;
        if (kt + 1 < KT) {
            int k0 = (kt + 1) * 8;
            if (tid < 128) ar = *(const float4*)&A[(m0 + arow) * K + k0 + acol];
            br = *(const float4*)&W[(n0 + brow) * K + k0 + bcol];
        }

        const float (*Ac)[64]  = As[cur];
        const float (*Bc)[128] = Bs[cur];
        #pragma unroll
        for (int kk = 0; kk < 8; kk++) {
            float4 av = *(const float4*)&Ac[kk][ty * 4];
            ulonglong2 bp0 = *(const ulonglong2*)&Bc[kk][tx * 4];
            ulonglong2 bp1 = *(const ulonglong2*)&Bc[kk][64 + tx * 4];
            unsigned long long ad0 = pack2(av.x, av.x);
            unsigned long long ad1 = pack2(av.y, av.y);
            unsigned long long ad2 = pack2(av.z, av.z);
            unsigned long long ad3 = pack2(av.w, av.w);
            ffma2(acc[0][0], ad0, bp0.x); ffma2(acc[0][1], ad0, bp0.y);
            ffma2(acc[0][2], ad0, bp1.x); ffma2(acc[0][3], ad0, bp1.y);
            ffma2(acc[1][0], ad1, bp0.x); ffma2(acc[1][1], ad1, bp0.y);
            ffma2(acc[1][2], ad1, bp1.x); ffma2(acc[1][3], ad1, bp1.y);
            ffma2(acc[2][0], ad2, bp0.x); ffma2(acc[2][1], ad2, bp0.y);
            ffma2(acc[2][2], ad2, bp1.x); ffma2(acc[2][3], ad2, bp1.y);
            ffma2(acc[3][0], ad3, bp0.x); ffma2(acc[3][1], ad3, bp0.y);
            ffma2(acc[3][2], ad3, bp1.x); ffma2(acc[3][3], ad3, bp1.y);
        }

        if (kt + 1 < KT) {
            const int nxt = cur ^ 1;
            if (tid < 128) {
                As[nxt][acol + 0][arow] = ar.x; As[nxt][acol + 1][arow] = ar.y;
                As[nxt][acol + 2][arow] = ar.z; As[nxt][acol + 3][arow] = ar.w;
            }
            Bs[nxt][bcol + 0][brow] = br.x; Bs[nxt][bcol + 1][brow] = br.y;
            Bs[nxt][bcol + 2][brow] = br.z; Bs[nxt][bcol + 3][brow] = br.w;
        }
        __syncthreads();
    }

    const int nA = n0 + tx * 4;
    const float4 bia0 = *(const float4*)&bias[nA];
    const float4 bia1 = *(const float4*)&bias[nA + 64];
    #pragma unroll
    for (int i = 0; i < 4; i++) {
        int m = m0 + ty * 4 + i;
        float c0, c1, c2, c3, c4, c5, c6, c7;
        unpack2(acc[i][0], c0, c1); unpack2(acc[i][1], c2, c3);
        unpack2(acc[i][2], c4, c5); unpack2(acc[i][3], c6, c7);
        float4 r0, r1;
        r0.x = c0 + bia0.x; r0.y = c1 + bia0.y; r0.z = c2 + bia0.z; r0.w = c3 + bia0.w;
        r1.x = c4 + bia1.x; r1.y = c5 + bia1.y; r1.z = c6 + bia1.z; r1.w = c7 + bia1.w;
        if (ACT == 1) {
            r0.x = act_elu(r0.x); r0.y = act_elu(r0.y); r0.z = act_elu(r0.z); r0.w = act_elu(r0.w);
            r1.x = act_elu(r1.x); r1.y = act_elu(r1.y); r1.z = act_elu(r1.z); r1.w = act_elu(r1.w);
        }
        if (ACT == 2) {
            r0.x = act_gelu_tanh(r0.x); r0.y = act_gelu_tanh(r0.y);
            r0.z = act_gelu_tanh(r0.z); r0.w = act_gelu_tanh(r0.w);
            r1.x = act_gelu_tanh(r1.x); r1.y = act_gelu_tanh(r1.y);
            r1.z = act_gelu_tanh(r1.z); r1.w = act_gelu_tanh(r1.w);
        }
        *(float4*)&C[m * Nout + nA] = r0;
        *(float4*)&C[m * Nout + nA + 64] = r1;
    }
}

// ---------------- f32x2 SGEMM, BN=64 ----------------
template <int ACT>
__global__ __launch_bounds__(256)
void gemm64_kernel(const float* __restrict__ A, const float* __restrict__ W,
                   const float* __restrict__ bias, float* __restrict__ C,
                   int M, int Nout, int K)
{
    __shared__ __align__(16) float As[2][8][64];
    __shared__ __align__(16) float Bs[2][8][64];
    const int tid = threadIdx.x;
    const int tx = tid & 15;
    const int ty = tid >> 4;
    const int m0 = blockIdx.y * 64, n0 = blockIdx.x * 64;

    const int lrow = (tid & 127) >> 1, lcol = (tid & 1) * 4;

    unsigned long long acc[4][2];
    #pragma unroll
    for (int i = 0; i < 4; i++) { acc[i][0] = 0ull; acc[i][1] = 0ull; }

    const int KT = K >> 3;
    float4 lr;

    if (tid < 128) lr = *(const float4*)&A[(m0 + lrow) * K + lcol];
    else           lr = *(const float4*)&W[(n0 + lrow) * K + lcol];
    {
        float (*dst)[64] = (tid < 128) ? As[0] : Bs[0];
        dst[lcol + 0][lrow] = lr.x; dst[lcol + 1][lrow] = lr.y;
        dst[lcol + 2][lrow] = lr.z; dst[lcol + 3][lrow] = lr.w;
    }
    __syncthreads();

    for (int kt = 0; kt < KT; kt++) {
        const int cur = kt & 1;
        if (kt + 1 < KT) {
            int k0 = (kt + 1) * 8;
            if (tid < 128) lr = *(const float4*)&A[(m0 + lrow) * K + k0 + lcol];
            else           lr = *(const float4*)&W[(n0 + lrow) * K + k0 + lcol];
        }

        const float (*Ac)[64] = As[cur];
        const float (*Bc)[64] = Bs[cur];
        #pragma unroll
        for (int kk = 0; kk < 8; kk++) {
            float4 av = *(const float4*)&Ac[kk][ty * 4];
            ulonglong2 bp = *(const ulonglong2*)&Bc[kk][tx * 4];
            unsigned long long ad0 = pack2(av.x, av.x);
            unsigned long long ad1 = pack2(av.y, av.y);
            unsigned long long ad2 = pack2(av.z, av.z);
            unsigned long long ad3 = pack2(av.w, av.w);
            ffma2(acc[0][0], ad0, bp.x); ffma2(acc[0][1], ad0, bp.y);
            ffma2(acc[1][0], ad1, bp.x); ffma2(acc[1][1], ad1, bp.y);
            ffma2(acc[2][0], ad2, bp.x); ffma2(acc[2][1], ad2, bp.y);
            ffma2(acc[3][0], ad3, bp.x); ffma2(acc[3][1], ad3, bp.y);
        }

        if (kt + 1 < KT) {
            float (*dst)[64] = (tid < 128) ? As[cur ^ 1] : Bs[cur ^ 1];
            dst[lcol + 0][lrow] = lr.x; dst[lcol + 1][lrow] = lr.y;
            dst[lcol + 2][lrow] = lr.z; dst[lcol + 3][lrow] = lr.w;
        }
        __syncthreads();
    }

    const int nA = n0 + tx * 4;
    const float4 bia = *(const float4*)&bias[nA];
    #pragma unroll
    for (int i = 0; i < 4; i++) {
        int m = m0 + ty * 4 + i;
        float c0, c1, c2, c3;
        unpack2(acc[i][0], c0, c1); unpack2(acc[i][1], c2, c3);
        float4 r0;
        r0.x = c0 + bia.x; r0.y = c1 + bia.y; r0.z = c2 + bia.z; r0.w = c3 + bia.w;
        if (ACT == 1) {
            r0.x = act_elu(r0.x); r0.y = act_elu(r0.y);
            r0.z = act_elu(r0.z); r0.w = act_elu(r0.w);
        }
        if (ACT == 2) {
            r0.x = act_gelu_tanh(r0.x); r0.y = act_gelu_tanh(r0.y);
            r0.z = act_gelu_tanh(r0.z); r0.w = act_gelu_tanh(r0.w);
        }
        *(float4*)&C[m * Nout + nA] = r0;
    }
}

// ---------------- small fallback SGEMM (N=5 head only) ----------------
template <int ACT>
__global__ __launch_bounds__(256)
void gemm_kernel(const float* __restrict__ A, const float* __restrict__ W,
                 const float* __restrict__ bias, float* __restrict__ C,
                 int M, int Nout, int K)
{
    __shared__ float As[16][64];
    __shared__ float Bs[16][64];
    const int tid = threadIdx.x;
    const int tx = tid & 15, ty = tid >> 4;
    const int m0 = blockIdx.y * 64, n0 = blockIdx.x * 64;

    float acc[4][4] = {};

    for (int k0 = 0; k0 < K; k0 += 16) {
        #pragma unroll
        for (int i = tid; i < 1024; i += 256) {
            int r = i >> 4, kk = i & 15;
            int k = k0 + kk;
            As[kk][r] = (k < K) ? A[(m0 + r) * K + k] : 0.f;
            int n = n0 + r;
            Bs[kk][r] = (n < Nout && k < K) ? W[n * K + k] : 0.f;
        }
        __syncthreads();
        #pragma unroll
        for (int kk = 0; kk < 16; kk++) {
            float4 a = *(const float4*)&As[kk][ty * 4];
            float4 b = *(const float4*)&Bs[kk][tx * 4];
            float av[4] = {a.x, a.y, a.z, a.w};
            float bv[4] = {b.x, b.y, b.z, b.w};
            #pragma unroll
            for (int i = 0; i < 4; i++)
                #pragma unroll
                for (int j = 0; j < 4; j++)
                    acc[i][j] += av[i] * bv[j];
        }
        __syncthreads();
    }

    #pragma unroll
    for (int i = 0; i < 4; i++) {
        int m = m0 + ty * 4 + i;
        #pragma unroll
        for (int j = 0; j < 4; j++) {
            int n = n0 + tx * 4 + j;
            if (n < Nout) {
                float v = acc[i][j] + bias[n];
                if (ACT == 1) v = act_elu(v);
                if (ACT == 2) v = act_gelu_tanh(v);
                C[m * Nout + n] = v;
            }
        }
    }
}

// ---------------- GIN pre-init: pre = (1+eps)*x ----------------
__global__ __launch_bounds__(256)
void gin_init_kernel(const float* __restrict__ x, const float* __restrict__ gin_eps,
                     int l, float* __restrict__ pre)
{
    int i = (blockIdx.x * blockDim.x + threadIdx.x) * 4;
    float s = 1.f + gin_eps[l];
    float4 xv = *(const float4*)&x[i];
    float4 r;
    r.x = s * xv.x; r.y = s * xv.y; r.z = s * xv.z; r.w = s * xv.w;
    *(float4*)&pre[i] = r;
}

// ---------------- GIN edge aggregation (edge_index int32) ----------------
__global__ __launch_bounds__(256)
void gin_agg_kernel(const int* __restrict__ ei,
                    const float* __restrict__ x, float* __restrict__ pre)
{
    long long gid = (long long)blockIdx.x * blockDim.x + threadIdx.x;
    int e = (int)(gid >> 6);
    int c = ((int)gid & 63) * 4;
    if (e >= EE) return;
    int src = ei[e];
    int dst = ei[EE + e];
    float4 v = *(const float4*)&x[src * DD + c];
    float* a = &pre[dst * DD + c];
    atomicAdd(a + 0, v.x);
    atomicAdd(a + 1, v.y);
    atomicAdd(a + 2, v.z);
    atomicAdd(a + 3, v.w);
}

// ---------------- fused LayerNorm (+opt ELU) + residual ----------------
template <int ACT>
__global__ __launch_bounds__(256)
void ln_res_kernel(const float* __restrict__ in, const float* __restrict__ g,
                   const float* __restrict__ b, float* __restrict__ x)
{
    __shared__ float red[256];
    int row = blockIdx.x, tid = threadIdx.x;
    float v = in[row * DD + tid];

    red[tid] = v;
    __syncthreads();
    #pragma unroll
    for (int s = 128; s > 0; s >>= 1) {
        if (tid < s) red[tid] += red[tid + s];
        __syncthreads();
    }
    float mu = red[0] * (1.f / DD);
    __syncthreads();

    float d = v - mu;
    red[tid] = d * d;
    __syncthreads();
    #pragma unroll
    for (int s = 128; s > 0; s >>= 1) {
        if (tid < s) red[tid] += red[tid + s];
        __syncthreads();
    }
    float var = red[0] * (1.f / DD);

    float y = d * rsqrtf(var + 1e-5f) * g[tid] + b[tid];
    if (ACT == 1) y = act_elu(y);
    x[row * DD + tid] += y;
}

// ---------------- flash attention via tf32 mma.sync ----------------
// Block = 128 threads (4 warps), 64 q-rows; warp w owns rows w*16..w*16+15.
// grid = (N/64, H). K/V staged in smem pre-converted to tf32; P round-trips
// through smem (C-frag layout -> A-frag layout), same warp => __syncwarp.
__global__ __launch_bounds__(128)
void flash_mma_kernel(const float* __restrict__ qkv, float* __restrict__ out)
{
    __shared__ __align__(16) unsigned Ks[64][36];
    __shared__ __align__(16) unsigned Vs[64][36];
    __shared__ __align__(16) unsigned Ps[64][66];

    const int tid = threadIdx.x;
    const int lane = tid & 31;
    const int wid = tid >> 5;
    const int hh = blockIdx.y;
    const int q0 = blockIdx.x * 64;
    const int gr = lane >> 2;   // 0..7
    const int gq = lane & 3;    // 0..3
    const float scale = 0.17677669529663689f;  // 1/sqrt(32)

    const int r0 = wid * 16 + gr;   // local row for frags {0,1}... a0/a2, c0/c1
    const int r1 = r0 + 8;

    // Q A-fragments (tf32, scale folded): aq[kk][0..3], kk = k-step 0..3
    unsigned aq[4][4];
    {
        const float* p0 = &qkv[(q0 + r0) * 768 + hh * 32];
        const float* p1 = &qkv[(q0 + r1) * 768 + hh * 32];
        #pragma unroll
        for (int kk = 0; kk < 4; kk++) {
            aq[kk][0] = cvt_tf32(p0[kk * 8 + gq] * scale);
            aq[kk][1] = cvt_tf32(p1[kk * 8 + gq] * scale);
            aq[kk][2] = cvt_tf32(p0[kk * 8 + gq + 4] * scale);
            aq[kk][3] = cvt_tf32(p1[kk * 8 + gq + 4] * scale);
        }
    }

    float m0 = -1e30f, l0 = 0.f, m1 = -1e30f, l1 = 0.f;
    float o[4][4];
    #pragma unroll
    for (int n = 0; n < 4; n++)
        #pragma unroll
        for (int f = 0; f < 4; f++) o[n][f] = 0.f;

    for (int t0 = 0; t0 < NN; t0 += 64) {
        __syncthreads();   // K/V smem reuse guard
        #pragma unroll
        for (int i = tid; i < 512; i += 128) {
            int r = i >> 3, d = (i & 7) * 4;
            float4 kv = *(const float4*)&qkv[(t0 + r) * 768 + 256 + hh * 32 + d];
            float4 vv = *(const float4*)&qkv[(t0 + r) * 768 + 512 + hh * 32 + d];
            uint4 kt, vt;
            kt.x = cvt_tf32(kv.x); kt.y = cvt_tf32(kv.y);
            kt.z = cvt_tf32(kv.z); kt.w = cvt_tf32(kv.w);
            vt.x = cvt_tf32(vv.x); vt.y = cvt_tf32(vv.y);
            vt.z = cvt_tf32(vv.z); vt.w = cvt_tf32(vv.w);
            *(uint4*)&Ks[r][d] = kt;
            *(uint4*)&Vs[r][d] = vt;
        }
        __syncthreads();

        // ---- S = Q K^T : 8 n-tiles x 4 k-steps ----
        float sc[8][4];
        #pragma unroll
        for (int nn = 0; nn < 8; nn++) {
            sc[nn][0] = 0.f; sc[nn][1] = 0.f; sc[nn][2] = 0.f; sc[nn][3] = 0.f;
            #pragma unroll
            for (int kk = 0; kk < 4; kk++) {
                unsigned b0 = Ks[nn * 8 + gr][kk * 8 + gq];
                unsigned b1 = Ks[nn * 8 + gr][kk * 8 + gq + 4];
                mma_tf32(sc[nn], aq[kk], b0, b1);
            }
        }

        // ---- online softmax (rows r0, r1) ----
        float rmax0 = -1e30f, rmax1 = -1e30f;
        #pragma unroll
        for (int nn = 0; nn < 8; nn++) {
            rmax0 = fmaxf(rmax0, fmaxf(sc[nn][0], sc[nn][1]));
            rmax1 = fmaxf(rmax1, fmaxf(sc[nn][2], sc[nn][3]));
        }
        rmax0 = fmaxf(rmax0, __shfl_xor_sync(0xffffffffu, rmax0, 1));
        rmax0 = fmaxf(rmax0, __shfl_xor_sync(0xffffffffu, rmax0, 2));
        rmax1 = fmaxf(rmax1, __shfl_xor_sync(0xffffffffu, rmax1, 1));
        rmax1 = fmaxf(rmax1, __shfl_xor_sync(0xffffffffu, rmax1, 2));

        float nm0 = fmaxf(m0, rmax0), alpha0 = __expf(m0 - nm0);
        float nm1 = fmaxf(m1, rmax1), alpha1 = __expf(m1 - nm1);

        float ps0 = 0.f, ps1 = 0.f;
        #pragma unroll
        for (int nn = 0; nn < 8; nn++) {
            float p00 = __expf(sc[nn][0] - nm0);
            float p01 = __expf(sc[nn][1] - nm0);
            float p10 = __expf(sc[nn][2] - nm1);
            float p11 = __expf(sc[nn][3] - nm1);
            ps0 += p00 + p01;
            ps1 += p10 + p11;
            uint2 w0, w1;
            w0.x = cvt_tf32(p00); w0.y = cvt_tf32(p01);
            w1.x = cvt_tf32(p10); w1.y = cvt_tf32(p11);
            *(uint2*)&Ps[r0][nn * 8 + 2 * gq] = w0;
            *(uint2*)&Ps[r1][nn * 8 + 2 * gq] = w1;
        }
        ps0 += __shfl_xor_sync(0xffffffffu, ps0, 1);
        ps0 += __shfl_xor_sync(0xffffffffu, ps0, 2);
        ps1 += __shfl_xor_sync(0xffffffffu, ps1, 1);
        ps1 += __shfl_xor_sync(0xffffffffu, ps1, 2);

        l0 = l0 * alpha0 + ps0; m0 = nm0;
        l1 = l1 * alpha1 + ps1; m1 = nm1;

        #pragma unroll
        for (int nn = 0; nn < 4; nn++) {
            o[nn][0] *= alpha0; o[nn][1] *= alpha0;
            o[nn][2] *= alpha1; o[nn][3] *= alpha1;
        }

        __syncwarp();   // P written by this warp, read below by this warp

        // ---- O += P V : 4 n-tiles (32 dims) x 8 k-steps ----
        #pragma unroll
        for (int kk = 0; kk < 8; kk++) {
            unsigned pa[4];
            pa[0] = Ps[r0][kk * 8 + gq];
            pa[1] = Ps[r1][kk * 8 + gq];
            pa[2] = Ps[r0][kk * 8 + gq + 4];
            pa[3] = Ps[r1][kk * 8 + gq + 4];
            #pragma unroll
            for (int nn = 0; nn < 4; nn++) {
                unsigned b0 = Vs[kk * 8 + gq][nn * 8 + gr];
                unsigned b1 = Vs[kk * 8 + gq + 4][nn * 8 + gr];
                mma_tf32(o[nn], pa, b0, b1);
            }
        }
        __syncwarp();   // finish reading Ps before next tile overwrites
    }

    const float inv0 = 1.f / l0, inv1 = 1.f / l1;
    #pragma unroll
    for (int nn = 0; nn < 4; nn++) {
        float2 w0, w1;
        w0.x = o[nn][0] * inv0; w0.y = o[nn][1] * inv0;
        w1.x = o[nn][2] * inv1; w1.y = o[nn][3] * inv1;
        *(float2*)&out[(q0 + r0) * DD + hh * 32 + nn * 8 + 2 * gq] = w0;
        *(float2*)&out[(q0 + r1) * DD + hh * 32 + nn * 8 + 2 * gq] = w1;
    }
}

// ---------------- host orchestration ----------------
extern "C" void kernel_launch(void* const* d_in, const int* in_sizes, int n_in,
                              void* d_out, int out_size)
{
    const float*     x         = (const float*)d_in[0];
    const int*       ei        = (const int*)d_in[1];
    const float*     in_w      = (const float*)d_in[2];
    const float*     in_b      = (const float*)d_in[3];
    const float*     head_w1   = (const float*)d_in[4];
    const float*     head_b1   = (const float*)d_in[5];
    const float*     head_w2   = (const float*)d_in[6];
    const float*     head_b2   = (const float*)d_in[7];
    const float*     mlp_w1    = (const float*)d_in[8];
    const float*     mlp_b1    = (const float*)d_in[9];
    const float*     mlp_w2    = (const float*)d_in[10];
    const float*     mlp_b2    = (const float*)d_in[11];
    const float*     gin_eps   = (const float*)d_in[12];
    const float*     ln1_g     = (const float*)d_in[13];
    const float*     ln1_b     = (const float*)d_in[14];
    const float*     attn_in_w = (const float*)d_in[15];
    const float*     attn_in_b = (const float*)d_in[16];
    const float*     attn_out_w= (const float*)d_in[17];
    const float*     attn_out_b= (const float*)d_in[18];
    const float*     ln2_g     = (const float*)d_in[19];
    const float*     ln2_b     = (const float*)d_in[20];
    const float*     ffn_w1    = (const float*)d_in[21];
    const float*     ffn_b1    = (const float*)d_in[22];
    const float*     ffn_w2    = (const float*)d_in[23];
    const float*     ffn_b2    = (const float*)d_in[24];
    const float*     ln3_g     = (const float*)d_in[25];
    const float*     ln3_b     = (const float*)d_in[26];

    float *h, *pre, *t, *t2, *ao, *emb;
    cudaGetSymbolAddress((void**)&h,   g_h);
    cudaGetSymbolAddress((void**)&pre, g_pre);
    cudaGetSymbolAddress((void**)&t,   g_t);
    cudaGetSymbolAddress((void**)&t2,  g_t2);
    cudaGetSymbolAddress((void**)&ao,  g_ao);
    cudaGetSymbolAddress((void**)&emb, g_emb);

    // input proj + ELU
    gemm64_kernel<1><<<dim3(DD / 64, NN / 64), 256>>>(x, in_w, in_b, h, NN, DD, DIN);

    for (int l = 0; l < 2; l++) {
        // ---- GIN ----
        gin_init_kernel<<<(NN * DD / 4) / 256, 256>>>(h, gin_eps, l, pre);
        gin_agg_kernel<<<(EE * 64) / 256, 256>>>(ei, h, pre);
        gemm64_kernel<1><<<dim3(DD / 64, NN / 64), 256>>>(
            pre, mlp_w1 + (size_t)l * DD * DD, mlp_b1 + (size_t)l * DD, t, NN, DD, DD);
        gemm64_kernel<0><<<dim3(DD / 64, NN / 64), 256>>>(
            t, mlp_w2 + (size_t)l * DD * DD, mlp_b2 + (size_t)l * DD, t2, NN, DD, DD);
        ln_res_kernel<1><<<NN, 256>>>(t2, ln1_g + (size_t)l * DD, ln1_b + (size_t)l * DD, h);

        // ---- global attention ----
        gemm_f2_kernel<0><<<dim3(768 / 128, NN / 64), 256>>>(
            h, attn_in_w + (size_t)l * 768 * DD, attn_in_b + (size_t)l * 768, t, NN, 768, DD);
        flash_mma_kernel<<<dim3(NN / 64, HH), 128>>>(t, ao);
        gemm64_kernel<0><<<dim3(DD / 64, NN / 64), 256>>>(
            ao, attn_out_w + (size_t)l * DD * DD, attn_out_b + (size_t)l * DD, t2, NN, DD, DD);
        ln_res_kernel<0><<<NN, 256>>>(t2, ln2_g + (size_t)l * DD, ln2_b + (size_t)l * DD, h);

        // ---- FFN ----
        gemm_f2_kernel<2><<<dim3(512 / 128, NN / 64), 256>>>(
            h, ffn_w1 + (size_t)l * 512 * DD, ffn_b1 + (size_t)l * 512, t, NN, 512, DD);
        gemm64_kernel<0><<<dim3(DD / 64, NN / 64), 256>>>(
            t, ffn_w2 + (size_t)l * DD * 512, ffn_b2 + (size_t)l * DD, t2, NN, DD, 512);
        ln_res_kernel<0><<<NN, 256>>>(t2, ln3_g + (size_t)l * DD, ln3_b + (size_t)l * DD, h);
    }

    // ---- head ----
    gemm64_kernel<1><<<dim3(DEMB / 64, NN / 64), 256>>>(h, head_w1, head_b1, emb, NN, DEMB, DD);
    gemm_kernel<0><<<dim3(1, NN / 64), 256>>>(emb, head_w2, head_b2, (float*)d_out, NN, TT, DEMB);
}

// round 9
// speedup vs baseline: 3.4436x; 1.1422x over previous
#include <cuda_runtime.h>
#include <cuda_bf16.h>
#include <math.h>

#define NN 4096
#define EE 131072
#define DIN 72
#define DD 256
#define HH 8
#define HDD 32
#define DEMB 128
#define TT 5

// ---------------- scratch (device globals; no runtime allocation) ----------------
__device__ float g_h  [NN * DD];
__device__ float g_pre[NN * DD];
__device__ float g_t  [NN * 768];
__device__ float g_t2 [NN * DD];
__device__ float g_ao [NN * DD];
__device__ float g_emb[NN * DEMB];

// ---------------- tf32 mma helpers ----------------
__device__ __forceinline__ unsigned cvt_tf32(float x) {
    unsigned r;
    asm("cvt.rna.tf32.f32 %0, %1;" : "=r"(r) : "f"(x));
    return r;
}
__device__ __forceinline__ void mma_tf32(float* c, const unsigned* a,
                                         unsigned b0, unsigned b1) {
    asm volatile(
        "mma.sync.aligned.m16n8k8.row.col.f32.tf32.tf32.f32 "
        "{%0,%1,%2,%3}, {%4,%5,%6,%7}, {%8,%9}, {%0,%1,%2,%3};\n"
        : "+f"(c[0]), "+f"(c[1]), "+f"(c[2]), "+f"(c[3])
        : "r"(a[0]), "r"(a[1]), "r"(a[2]), "r"(a[3]), "r"(b0), "r"(b1));
}

// ---------------- activations ----------------
__device__ __forceinline__ float act_elu(float v) {
    return v > 0.f ? v : expm1f(v);
}
__device__ __forceinline__ float act_gelu_tanh(float v) {
    const float c = 0.7978845608028654f;   // sqrt(2/pi)
    float u = c * (v + 0.044715f * v * v * v);
    return 0.5f * v * (1.f + tanhf(u));
}

// ---------------- tf32 MMA GEMM: C = act(A @ W^T + b) ----------------
// A: [M,K] row-major fp32, W: [Nout,K] row-major fp32 (torch Linear weight).
// Block: 128 threads = 4 warps (2x2), tile 64x64, BK=32 (zero-filled tail).
// Requires M%64==0, Nout%64==0, K%4==0.
template <int ACT>
__global__ __launch_bounds__(128)
void gemm_mma_kernel(const float* __restrict__ A, const float* __restrict__ W,
                     const float* __restrict__ bias, float* __restrict__ C,
                     int M, int Nout, int K)
{
    __shared__ __align__(16) unsigned As[2][64][36];
    __shared__ __align__(16) unsigned Bs[2][64][36];

    const int tid = threadIdx.x;
    const int lane = tid & 31;
    const int wid = tid >> 5;
    const int gr = lane >> 2;      // 0..7
    const int gq = lane & 3;       // 0..3
    const int wm = (wid >> 1) * 32;
    const int wn = (wid & 1) * 32;
    const int m0 = blockIdx.y * 64, n0 = blockIdx.x * 64;

    float acc[2][4][4];
    #pragma unroll
    for (int mi = 0; mi < 2; mi++)
        #pragma unroll
        for (int ni = 0; ni < 4; ni++)
            #pragma unroll
            for (int f = 0; f < 4; f++) acc[mi][ni][f] = 0.f;

    const int KT = (K + 31) >> 5;

    // loader: 4 float4 per array per thread per tile
    // i in {tid, tid+128, tid+256, tid+384}: r = i>>3 (0..63), cg = i&7
    uint4 pa[4], pb[4];

    auto fetch = [&](int kt) {
        #pragma unroll
        for (int u = 0; u < 4; u++) {
            int i = tid + u * 128;
            int r = i >> 3, cg = i & 7;
            int k = kt * 32 + cg * 4;
            uint4 va = {0u, 0u, 0u, 0u}, vb = {0u, 0u, 0u, 0u};
            if (k < K) {
                float4 fa = *(const float4*)&A[(size_t)(m0 + r) * K + k];
                float4 fb = *(const float4*)&W[(size_t)(n0 + r) * K + k];
                va.x = cvt_tf32(fa.x); va.y = cvt_tf32(fa.y);
                va.z = cvt_tf32(fa.z); va.w = cvt_tf32(fa.w);
                vb.x = cvt_tf32(fb.x); vb.y = cvt_tf32(fb.y);
                vb.z = cvt_tf32(fb.z); vb.w = cvt_tf32(fb.w);
            }
            pa[u] = va; pb[u] = vb;
        }
    };
    auto stash = [&](int buf) {
        #pragma unroll
        for (int u = 0; u < 4; u++) {
            int i = tid + u * 128;
            int r = i >> 3, cg = i & 7;
            *(uint4*)&As[buf][r][cg * 4] = pa[u];
            *(uint4*)&Bs[buf][r][cg * 4] = pb[u];
        }
    };

    fetch(0);
    stash(0);
    __syncthreads();

    for (int kt = 0; kt < KT; kt++) {
        const int cur = kt & 1;
        if (kt + 1 < KT) fetch(kt + 1);

        const unsigned (*Ac)[36] = As[cur];
        const unsigned (*Bc)[36] = Bs[cur];
        #pragma unroll
        for (int kk = 0; kk < 4; kk++) {
            unsigned a[2][4];
            #pragma unroll
            for (int mi = 0; mi < 2; mi++) {
                const int rr = wm + mi * 16 + gr;
                a[mi][0] = Ac[rr][kk * 8 + gq];
                a[mi][1] = Ac[rr + 8][kk * 8 + gq];
                a[mi][2] = Ac[rr][kk * 8 + gq + 4];
                a[mi][3] = Ac[rr + 8][kk * 8 + gq + 4];
            }
            #pragma unroll
            for (int ni = 0; ni < 4; ni++) {
                unsigned b0 = Bc[wn + ni * 8 + gr][kk * 8 + gq];
                unsigned b1 = Bc[wn + ni * 8 + gr][kk * 8 + gq + 4];
                mma_tf32(acc[0][ni], a[0], b0, b1);
                mma_tf32(acc[1][ni], a[1], b0, b1);
            }
        }

        if (kt + 1 < KT) stash(cur ^ 1);
        __syncthreads();
    }

    // epilogue: C-frag rows gr/gr+8, cols 2gq/2gq+1 per n-tile
    #pragma unroll
    for (int mi = 0; mi < 2; mi++) {
        const int m = m0 + wm + mi * 16 + gr;
        #pragma unroll
        for (int ni = 0; ni < 4; ni++) {
            const int n = n0 + wn + ni * 8 + 2 * gq;
            float b0 = bias[n], b1 = bias[n + 1];
            float2 w0, w1;
            w0.x = acc[mi][ni][0] + b0; w0.y = acc[mi][ni][1] + b1;
            w1.x = acc[mi][ni][2] + b0; w1.y = acc[mi][ni][3] + b1;
            if (ACT == 1) {
                w0.x = act_elu(w0.x); w0.y = act_elu(w0.y);
                w1.x = act_elu(w1.x); w1.y = act_elu(w1.y);
            }
            if (ACT == 2) {
                w0.x = act_gelu_tanh(w0.x); w0.y = act_gelu_tanh(w0.y);
                w1.x = act_gelu_tanh(w1.x); w1.y = act_gelu_tanh(w1.y);
            }
            *(float2*)&C[(size_t)m * Nout + n] = w0;
            *(float2*)&C[(size_t)(m + 8) * Nout + n] = w1;
        }
    }
}

// ---------------- small fallback SGEMM (N=5 head only) ----------------
template <int ACT>
__global__ __launch_bounds__(256)
void gemm_kernel(const float* __restrict__ A, const float* __restrict__ W,
                 const float* __restrict__ bias, float* __restrict__ C,
                 int M, int Nout, int K)
{
    __shared__ float As[16][64];
    __shared__ float Bs[16][64];
    const int tid = threadIdx.x;
    const int tx = tid & 15, ty = tid >> 4;
    const int m0 = blockIdx.y * 64, n0 = blockIdx.x * 64;

    float acc[4][4] = {};

    for (int k0 = 0; k0 < K; k0 += 16) {
        #pragma unroll
        for (int i = tid; i < 1024; i += 256) {
            int r = i >> 4, kk = i & 15;
            int k = k0 + kk;
            As[kk][r] = (k < K) ? A[(m0 + r) * K + k] : 0.f;
            int n = n0 + r;
            Bs[kk][r] = (n < Nout && k < K) ? W[n * K + k] : 0.f;
        }
        __syncthreads();
        #pragma unroll
        for (int kk = 0; kk < 16; kk++) {
            float4 a = *(const float4*)&As[kk][ty * 4];
            float4 b = *(const float4*)&Bs[kk][tx * 4];
            float av[4] = {a.x, a.y, a.z, a.w};
            float bv[4] = {b.x, b.y, b.z, b.w};
            #pragma unroll
            for (int i = 0; i < 4; i++)
                #pragma unroll
                for (int j = 0; j < 4; j++)
                    acc[i][j] += av[i] * bv[j];
        }
        __syncthreads();
    }

    #pragma unroll
    for (int i = 0; i < 4; i++) {
        int m = m0 + ty * 4 + i;
        #pragma unroll
        for (int j = 0; j < 4; j++) {
            int n = n0 + tx * 4 + j;
            if (n < Nout) {
                float v = acc[i][j] + bias[n];
                if (ACT == 1) v = act_elu(v);
                if (ACT == 2) v = act_gelu_tanh(v);
                C[m * Nout + n] = v;
            }
        }
    }
}

// ---------------- GIN pre-init: pre = (1+eps)*x ----------------
__global__ __launch_bounds__(256)
void gin_init_kernel(const float* __restrict__ x, const float* __restrict__ gin_eps,
                     int l, float* __restrict__ pre)
{
    int i = (blockIdx.x * blockDim.x + threadIdx.x) * 4;
    float s = 1.f + gin_eps[l];
    float4 xv = *(const float4*)&x[i];
    float4 r;
    r.x = s * xv.x; r.y = s * xv.y; r.z = s * xv.z; r.w = s * xv.w;
    *(float4*)&pre[i] = r;
}

// ---------------- GIN edge aggregation (edge_index int32) ----------------
__global__ __launch_bounds__(256)
void gin_agg_kernel(const int* __restrict__ ei,
                    const float* __restrict__ x, float* __restrict__ pre)
{
    long long gid = (long long)blockIdx.x * blockDim.x + threadIdx.x;
    int e = (int)(gid >> 6);
    int c = ((int)gid & 63) * 4;
    if (e >= EE) return;
    int src = ei[e];
    int dst = ei[EE + e];
    float4 v = *(const float4*)&x[src * DD + c];
    float* a = &pre[dst * DD + c];
    atomicAdd(a + 0, v.x);
    atomicAdd(a + 1, v.y);
    atomicAdd(a + 2, v.z);
    atomicAdd(a + 3, v.w);
}

// ---------------- fused LayerNorm (+opt ELU) + residual ----------------
template <int ACT>
__global__ __launch_bounds__(256)
void ln_res_kernel(const float* __restrict__ in, const float* __restrict__ g,
                   const float* __restrict__ b, float* __restrict__ x)
{
    __shared__ float red[256];
    int row = blockIdx.x, tid = threadIdx.x;
    float v = in[row * DD + tid];

    red[tid] = v;
    __syncthreads();
    #pragma unroll
    for (int s = 128; s > 0; s >>= 1) {
        if (tid < s) red[tid] += red[tid + s];
        __syncthreads();
    }
    float mu = red[0] * (1.f / DD);
    __syncthreads();

    float d = v - mu;
    red[tid] = d * d;
    __syncthreads();
    #pragma unroll
    for (int s = 128; s > 0; s >>= 1) {
        if (tid < s) red[tid] += red[tid + s];
        __syncthreads();
    }
    float var = red[0] * (1.f / DD);

    float y = d * rsqrtf(var + 1e-5f) * g[tid] + b[tid];
    if (ACT == 1) y = act_elu(y);
    x[row * DD + tid] += y;
}

// ---------------- flash attention via tf32 mma.sync ----------------
__global__ __launch_bounds__(128)
void flash_mma_kernel(const float* __restrict__ qkv, float* __restrict__ out)
{
    __shared__ __align__(16) unsigned Ks[64][36];
    __shared__ __align__(16) unsigned Vs[64][36];
    __shared__ __align__(16) unsigned Ps[64][66];

    const int tid = threadIdx.x;
    const int lane = tid & 31;
    const int wid = tid >> 5;
    const int hh = blockIdx.y;
    const int q0 = blockIdx.x * 64;
    const int gr = lane >> 2;
    const int gq = lane & 3;
    const float scale = 0.17677669529663689f;  // 1/sqrt(32)

    const int r0 = wid * 16 + gr;
    const int r1 = r0 + 8;

    unsigned aq[4][4];
    {
        const float* p0 = &qkv[(q0 + r0) * 768 + hh * 32];
        const float* p1 = &qkv[(q0 + r1) * 768 + hh * 32];
        #pragma unroll
        for (int kk = 0; kk < 4; kk++) {
            aq[kk][0] = cvt_tf32(p0[kk * 8 + gq] * scale);
            aq[kk][1] = cvt_tf32(p1[kk * 8 + gq] * scale);
            aq[kk][2] = cvt_tf32(p0[kk * 8 + gq + 4] * scale);
            aq[kk][3] = cvt_tf32(p1[kk * 8 + gq + 4] * scale);
        }
    }

    float m0 = -1e30f, l0 = 0.f, m1 = -1e30f, l1 = 0.f;
    float o[4][4];
    #pragma unroll
    for (int n = 0; n < 4; n++)
        #pragma unroll
        for (int f = 0; f < 4; f++) o[n][f] = 0.f;

    for (int t0 = 0; t0 < NN; t0 += 64) {
        __syncthreads();
        #pragma unroll
        for (int i = tid; i < 512; i += 128) {
            int r = i >> 3, d = (i & 7) * 4;
            float4 kv = *(const float4*)&qkv[(t0 + r) * 768 + 256 + hh * 32 + d];
            float4 vv = *(const float4*)&qkv[(t0 + r) * 768 + 512 + hh * 32 + d];
            uint4 kt, vt;
            kt.x = cvt_tf32(kv.x); kt.y = cvt_tf32(kv.y);
            kt.z = cvt_tf32(kv.z); kt.w = cvt_tf32(kv.w);
            vt.x = cvt_tf32(vv.x); vt.y = cvt_tf32(vv.y);
            vt.z = cvt_tf32(vv.z); vt.w = cvt_tf32(vv.w);
            *(uint4*)&Ks[r][d] = kt;
            *(uint4*)&Vs[r][d] = vt;
        }
        __syncthreads();

        float sc[8][4];
        #pragma unroll
        for (int nn = 0; nn < 8; nn++) {
            sc[nn][0] = 0.f; sc[nn][1] = 0.f; sc[nn][2] = 0.f; sc[nn][3] = 0.f;
            #pragma unroll
            for (int kk = 0; kk < 4; kk++) {
                unsigned b0 = Ks[nn * 8 + gr][kk * 8 + gq];
                unsigned b1 = Ks[nn * 8 + gr][kk * 8 + gq + 4];
                mma_tf32(sc[nn], aq[kk], b0, b1);
            }
        }

        float rmax0 = -1e30f, rmax1 = -1e30f;
        #pragma unroll
        for (int nn = 0; nn < 8; nn++) {
            rmax0 = fmaxf(rmax0, fmaxf(sc[nn][0], sc[nn][1]));
            rmax1 = fmaxf(rmax1, fmaxf(sc[nn][2], sc[nn][3]));
        }
        rmax0 = fmaxf(rmax0, __shfl_xor_sync(0xffffffffu, rmax0, 1));
        rmax0 = fmaxf(rmax0, __shfl_xor_sync(0xffffffffu, rmax0, 2));
        rmax1 = fmaxf(rmax1, __shfl_xor_sync(0xffffffffu, rmax1, 1));
        rmax1 = fmaxf(rmax1, __shfl_xor_sync(0xffffffffu, rmax1, 2));

        float nm0 = fmaxf(m0, rmax0), alpha0 = __expf(m0 - nm0);
        float nm1 = fmaxf(m1, rmax1), alpha1 = __expf(m1 - nm1);

        float ps0 = 0.f, ps1 = 0.f;
        #pragma unroll
        for (int nn = 0; nn < 8; nn++) {
            float p00 = __expf(sc[nn][0] - nm0);
            float p01 = __expf(sc[nn][1] - nm0);
            float p10 = __expf(sc[nn][2] - nm1);
            float p11 = __expf(sc[nn][3] - nm1);
            ps0 += p00 + p01;
            ps1 += p10 + p11;
            uint2 w0, w1;
            w0.x = cvt_tf32(p00); w0.y = cvt_tf32(p01);
            w1.x = cvt_tf32(p10); w1.y = cvt_tf32(p11);
            *(uint2*)&Ps[r0][nn * 8 + 2 * gq] = w0;
            *(uint2*)&Ps[r1][nn * 8 + 2 * gq] = w1;
        }
        ps0 += __shfl_xor_sync(0xffffffffu, ps0, 1);
        ps0 += __shfl_xor_sync(0xffffffffu, ps0, 2);
        ps1 += __shfl_xor_sync(0xffffffffu, ps1, 1);
        ps1 += __shfl_xor_sync(0xffffffffu, ps1, 2);

        l0 = l0 * alpha0 + ps0; m0 = nm0;
        l1 = l1 * alpha1 + ps1; m1 = nm1;

        #pragma unroll
        for (int nn = 0; nn < 4; nn++) {
            o[nn][0] *= alpha0; o[nn][1] *= alpha0;
            o[nn][2] *= alpha1; o[nn][3] *= alpha1;
        }

        __syncwarp();

        #pragma unroll
        for (int kk = 0; kk < 8; kk++) {
            unsigned pa[4];
            pa[0] = Ps[r0][kk * 8 + gq];
            pa[1] = Ps[r1][kk * 8 + gq];
            pa[2] = Ps[r0][kk * 8 + gq + 4];
            pa[3] = Ps[r1][kk * 8 + gq + 4];
            #pragma unroll
            for (int nn = 0; nn < 4; nn++) {
                unsigned b0 = Vs[kk * 8 + gq][nn * 8 + gr];
                unsigned b1 = Vs[kk * 8 + gq + 4][nn * 8 + gr];
                mma_tf32(o[nn], pa, b0, b1);
            }
        }
        __syncwarp();
    }

    const float inv0 = 1.f / l0, inv1 = 1.f / l1;
    #pragma unroll
    for (int nn = 0; nn < 4; nn++) {
        float2 w0, w1;
        w0.x = o[nn][0] * inv0; w0.y = o[nn][1] * inv0;
        w1.x = o[nn][2] * inv1; w1.y = o[nn][3] * inv1;
        *(float2*)&out[(q0 + r0) * DD + hh * 32 + nn * 8 + 2 * gq] = w0;
        *(float2*)&out[(q0 + r1) * DD + hh * 32 + nn * 8 + 2 * gq] = w1;
    }
}

// ---------------- host orchestration ----------------
extern "C" void kernel_launch(void* const* d_in, const int* in_sizes, int n_in,
                              void* d_out, int out_size)
{
    const float*     x         = (const float*)d_in[0];
    const int*       ei        = (const int*)d_in[1];
    const float*     in_w      = (const float*)d_in[2];
    const float*     in_b      = (const float*)d_in[3];
    const float*     head_w1   = (const float*)d_in[4];
    const float*     head_b1   = (const float*)d_in[5];
    const float*     head_w2   = (const float*)d_in[6];
    const float*     head_b2   = (const float*)d_in[7];
    const float*     mlp_w1    = (const float*)d_in[8];
    const float*     mlp_b1    = (const float*)d_in[9];
    const float*     mlp_w2    = (const float*)d_in[10];
    const float*     mlp_b2    = (const float*)d_in[11];
    const float*     gin_eps   = (const float*)d_in[12];
    const float*     ln1_g     = (const float*)d_in[13];
    const float*     ln1_b     = (const float*)d_in[14];
    const float*     attn_in_w = (const float*)d_in[15];
    const float*     attn_in_b = (const float*)d_in[16];
    const float*     attn_out_w= (const float*)d_in[17];
    const float*     attn_out_b= (const float*)d_in[18];
    const float*     ln2_g     = (const float*)d_in[19];
    const float*     ln2_b     = (const float*)d_in[20];
    const float*     ffn_w1    = (const float*)d_in[21];
    const float*     ffn_b1    = (const float*)d_in[22];
    const float*     ffn_w2    = (const float*)d_in[23];
    const float*     ffn_b2    = (const float*)d_in[24];
    const float*     ln3_g     = (const float*)d_in[25];
    const float*     ln3_b     = (const float*)d_in[26];

    float *h, *pre, *t, *t2, *ao, *emb;
    cudaGetSymbolAddress((void**)&h,   g_h);
    cudaGetSymbolAddress((void**)&pre, g_pre);
    cudaGetSymbolAddress((void**)&t,   g_t);
    cudaGetSymbolAddress((void**)&t2,  g_t2);
    cudaGetSymbolAddress((void**)&ao,  g_ao);
    cudaGetSymbolAddress((void**)&emb, g_emb);

    // input proj + ELU
    gemm_mma_kernel<1><<<dim3(DD / 64, NN / 64), 128>>>(x, in_w, in_b, h, NN, DD, DIN);

    for (int l = 0; l < 2; l++) {
        // ---- GIN ----
        gin_init_kernel<<<(NN * DD / 4) / 256, 256>>>(h, gin_eps, l, pre);
        gin_agg_kernel<<<(EE * 64) / 256, 256>>>(ei, h, pre);
        gemm_mma_kernel<1><<<dim3(DD / 64, NN / 64), 128>>>(
            pre, mlp_w1 + (size_t)l * DD * DD, mlp_b1 + (size_t)l * DD, t, NN, DD, DD);
        gemm_mma_kernel<0><<<dim3(DD / 64, NN / 64), 128>>>(
            t, mlp_w2 + (size_t)l * DD * DD, mlp_b2 + (size_t)l * DD, t2, NN, DD, DD);
        ln_res_kernel<1><<<NN, 256>>>(t2, ln1_g + (size_t)l * DD, ln1_b + (size_t)l * DD, h);

        // ---- global attention ----
        gemm_mma_kernel<0><<<dim3(768 / 64, NN / 64), 128>>>(
            h, attn_in_w + (size_t)l * 768 * DD, attn_in_b + (size_t)l * 768, t, NN, 768, DD);
        flash_mma_kernel<<<dim3(NN / 64, HH), 128>>>(t, ao);
        gemm_mma_kernel<0><<<dim3(DD / 64, NN / 64), 128>>>(
            ao, attn_out_w + (size_t)l * DD * DD, attn_out_b + (size_t)l * DD, t2, NN, DD, DD);
        ln_res_kernel<0><<<NN, 256>>>(t2, ln2_g + (size_t)l * DD, ln2_b + (size_t)l * DD, h);

        // ---- FFN ----
        gemm_mma_kernel<2><<<dim3(512 / 64, NN / 64), 128>>>(
            h, ffn_w1 + (size_t)l * 512 * DD, ffn_b1 + (size_t)l * 512, t, NN, 512, DD);
        gemm_mma_kernel<0><<<dim3(DD / 64, NN / 64), 128>>>(
            t, ffn_w2 + (size_t)l * DD * 512, ffn_b2 + (size_t)l * DD, t2, NN, DD, 512);
        ln_res_kernel<0><<<NN, 256>>>(t2, ln3_g + (size_t)l * DD, ln3_b + (size_t)l * DD, h);
    }

    // ---- head ----
    gemm_mma_kernel<1><<<dim3(DEMB / 64, NN / 64), 128>>>(h, head_w1, head_b1, emb, NN, DEMB, DD);
    gemm_kernel<0><<<dim3(1, NN / 64), 256>>>(emb, head_w2, head_b2, (float*)d_out, NN, TT, DEMB);
}

// round 10
// speedup vs baseline: 4.2229x; 1.2263x over previous
#include <cuda_runtime.h>
#include <cuda_bf16.h>
#include <math.h>

#define NN 4096
#define EE 131072
#define DIN 72
#define DD 256
#define HH 8
#define HDD 32
#define DEMB 128
#define TT 5

// ---------------- scratch (device globals; no runtime allocation) ----------------
__device__ float g_h  [NN * DD];
__device__ float g_pre[NN * DD];
__device__ float g_t  [NN * 768];
__device__ float g_t2 [NN * DD];
__device__ float g_ao [NN * DD];
__device__ float g_emb[NN * DEMB];

// ---------------- tf32 mma helpers ----------------
__device__ __forceinline__ unsigned cvt_tf32(float x) {
    unsigned r;
    asm("cvt.rna.tf32.f32 %0, %1;" : "=r"(r) : "f"(x));
    return r;
}
__device__ __forceinline__ void mma_tf32(float* c, const unsigned* a,
                                         unsigned b0, unsigned b1) {
    asm volatile(
        "mma.sync.aligned.m16n8k8.row.col.f32.tf32.tf32.f32 "
        "{%0,%1,%2,%3}, {%4,%5,%6,%7}, {%8,%9}, {%0,%1,%2,%3};\n"
        : "+f"(c[0]), "+f"(c[1]), "+f"(c[2]), "+f"(c[3])
        : "r"(a[0]), "r"(a[1]), "r"(a[2]), "r"(a[3]), "r"(b0), "r"(b1));
}

// ---------------- activations ----------------
__device__ __forceinline__ float act_elu(float v) {
    return v > 0.f ? v : expm1f(v);
}
__device__ __forceinline__ float act_gelu_tanh(float v) {
    const float c = 0.7978845608028654f;   // sqrt(2/pi)
    float u = c * (v + 0.044715f * v * v * v);
    return 0.5f * v * (1.f + tanhf(u));
}

// ---------------- tf32 MMA GEMM: C = act(A @ W^T + b) ----------------
// Block: 256 threads = 8 warps (4x2), tile 64x64, BK=32 (zero-filled tail).
// Warp sub-tile 16x32: short per-warp critical path, 2x warps for latency hiding.
// Requires M%64==0, Nout%64==0, K%4==0.
template <int ACT>
__global__ __launch_bounds__(256)
void gemm_mma_kernel(const float* __restrict__ A, const float* __restrict__ W,
                     const float* __restrict__ bias, float* __restrict__ C,
                     int M, int Nout, int K)
{
    __shared__ __align__(16) unsigned As[2][64][36];
    __shared__ __align__(16) unsigned Bs[2][64][36];

    const int tid = threadIdx.x;
    const int lane = tid & 31;
    const int wid = tid >> 5;      // 0..7
    const int gr = lane >> 2;      // 0..7
    const int gq = lane & 3;       // 0..3
    const int wm = (wid >> 1) * 16;   // 0,16,32,48
    const int wn = (wid & 1) * 32;    // 0,32
    const int m0 = blockIdx.y * 64, n0 = blockIdx.x * 64;

    float acc[4][4];
    #pragma unroll
    for (int ni = 0; ni < 4; ni++)
        #pragma unroll
        for (int f = 0; f < 4; f++) acc[ni][f] = 0.f;

    const int KT = (K + 31) >> 5;

    // loader: 2 float4 per array per thread per k-tile
    uint4 pa[2], pb[2];

    auto fetch = [&](int kt) {
        #pragma unroll
        for (int u = 0; u < 2; u++) {
            int i = tid + u * 256;
            int r = i >> 3, cg = i & 7;
            int k = kt * 32 + cg * 4;
            uint4 va = {0u, 0u, 0u, 0u}, vb = {0u, 0u, 0u, 0u};
            if (k < K) {
                float4 fa = *(const float4*)&A[(size_t)(m0 + r) * K + k];
                float4 fb = *(const float4*)&W[(size_t)(n0 + r) * K + k];
                va.x = cvt_tf32(fa.x); va.y = cvt_tf32(fa.y);
                va.z = cvt_tf32(fa.z); va.w = cvt_tf32(fa.w);
                vb.x = cvt_tf32(fb.x); vb.y = cvt_tf32(fb.y);
                vb.z = cvt_tf32(fb.z); vb.w = cvt_tf32(fb.w);
            }
            pa[u] = va; pb[u] = vb;
        }
    };
    auto stash = [&](int buf) {
        #pragma unroll
        for (int u = 0; u < 2; u++) {
            int i = tid + u * 256;
            int r = i >> 3, cg = i & 7;
            *(uint4*)&As[buf][r][cg * 4] = pa[u];
            *(uint4*)&Bs[buf][r][cg * 4] = pb[u];
        }
    };

    fetch(0);
    stash(0);
    __syncthreads();

    for (int kt = 0; kt < KT; kt++) {
        const int cur = kt & 1;
        if (kt + 1 < KT) fetch(kt + 1);

        const unsigned (*Ac)[36] = As[cur];
        const unsigned (*Bc)[36] = Bs[cur];
        #pragma unroll
        for (int kk = 0; kk < 4; kk++) {
            unsigned a[4];
            const int rr = wm + gr;
            a[0] = Ac[rr][kk * 8 + gq];
            a[1] = Ac[rr + 8][kk * 8 + gq];
            a[2] = Ac[rr][kk * 8 + gq + 4];
            a[3] = Ac[rr + 8][kk * 8 + gq + 4];
            #pragma unroll
            for (int ni = 0; ni < 4; ni++) {
                unsigned b0 = Bc[wn + ni * 8 + gr][kk * 8 + gq];
                unsigned b1 = Bc[wn + ni * 8 + gr][kk * 8 + gq + 4];
                mma_tf32(acc[ni], a, b0, b1);
            }
        }

        if (kt + 1 < KT) stash(cur ^ 1);
        __syncthreads();
    }

    // epilogue: C-frag rows gr/gr+8, cols 2gq/2gq+1 per n-tile
    const int m = m0 + wm + gr;
    #pragma unroll
    for (int ni = 0; ni < 4; ni++) {
        const int n = n0 + wn + ni * 8 + 2 * gq;
        float b0 = bias[n], b1 = bias[n + 1];
        float2 w0, w1;
        w0.x = acc[ni][0] + b0; w0.y = acc[ni][1] + b1;
        w1.x = acc[ni][2] + b0; w1.y = acc[ni][3] + b1;
        if (ACT == 1) {
            w0.x = act_elu(w0.x); w0.y = act_elu(w0.y);
            w1.x = act_elu(w1.x); w1.y = act_elu(w1.y);
        }
        if (ACT == 2) {
            w0.x = act_gelu_tanh(w0.x); w0.y = act_gelu_tanh(w0.y);
            w1.x = act_gelu_tanh(w1.x); w1.y = act_gelu_tanh(w1.y);
        }
        *(float2*)&C[(size_t)m * Nout + n] = w0;
        *(float2*)&C[(size_t)(m + 8) * Nout + n] = w1;
    }
}

// ---------------- small fallback SGEMM (N=5 head only) ----------------
template <int ACT>
__global__ __launch_bounds__(256)
void gemm_kernel(const float* __restrict__ A, const float* __restrict__ W,
                 const float* __restrict__ bias, float* __restrict__ C,
                 int M, int Nout, int K)
{
    __shared__ float As[16][64];
    __shared__ float Bs[16][64];
    const int tid = threadIdx.x;
    const int tx = tid & 15, ty = tid >> 4;
    const int m0 = blockIdx.y * 64, n0 = blockIdx.x * 64;

    float acc[4][4] = {};

    for (int k0 = 0; k0 < K; k0 += 16) {
        #pragma unroll
        for (int i = tid; i < 1024; i += 256) {
            int r = i >> 4, kk = i & 15;
            int k = k0 + kk;
            As[kk][r] = (k < K) ? A[(m0 + r) * K + k] : 0.f;
            int n = n0 + r;
            Bs[kk][r] = (n < Nout && k < K) ? W[n * K + k] : 0.f;
        }
        __syncthreads();
        #pragma unroll
        for (int kk = 0; kk < 16; kk++) {
            float4 a = *(const float4*)&As[kk][ty * 4];
            float4 b = *(const float4*)&Bs[kk][tx * 4];
            float av[4] = {a.x, a.y, a.z, a.w};
            float bv[4] = {b.x, b.y, b.z, b.w};
            #pragma unroll
            for (int i = 0; i < 4; i++)
                #pragma unroll
                for (int j = 0; j < 4; j++)
                    acc[i][j] += av[i] * bv[j];
        }
        __syncthreads();
    }

    #pragma unroll
    for (int i = 0; i < 4; i++) {
        int m = m0 + ty * 4 + i;
        #pragma unroll
        for (int j = 0; j < 4; j++) {
            int n = n0 + tx * 4 + j;
            if (n < Nout) {
                float v = acc[i][j] + bias[n];
                if (ACT == 1) v = act_elu(v);
                if (ACT == 2) v = act_gelu_tanh(v);
                C[m * Nout + n] = v;
            }
        }
    }
}

// ---------------- GIN pre-init: pre = (1+eps)*x ----------------
__global__ __launch_bounds__(256)
void gin_init_kernel(const float* __restrict__ x, const float* __restrict__ gin_eps,
                     int l, float* __restrict__ pre)
{
    int i = (blockIdx.x * blockDim.x + threadIdx.x) * 4;
    float s = 1.f + gin_eps[l];
    float4 xv = *(const float4*)&x[i];
    float4 r;
    r.x = s * xv.x; r.y = s * xv.y; r.z = s * xv.z; r.w = s * xv.w;
    *(float4*)&pre[i] = r;
}

// ---------------- GIN edge aggregation: vector red.global.add.v4.f32 ----------------
__global__ __launch_bounds__(256)
void gin_agg_kernel(const int* __restrict__ ei,
                    const float* __restrict__ x, float* __restrict__ pre)
{
    long long gid = (long long)blockIdx.x * blockDim.x + threadIdx.x;
    int e = (int)(gid >> 6);
    int c = ((int)gid & 63) * 4;
    if (e >= EE) return;
    int src = ei[e];
    int dst = ei[EE + e];
    float4 v = *(const float4*)&x[src * DD + c];
    float* a = &pre[dst * DD + c];
    asm volatile("red.global.add.v4.f32 [%0], {%1, %2, %3, %4};"
                 :: "l"(a), "f"(v.x), "f"(v.y), "f"(v.z), "f"(v.w)
                 : "memory");
}

// ---------------- fused LayerNorm (+opt ELU) + residual, one-pass ----------------
template <int ACT>
__global__ __launch_bounds__(256)
void ln_res_kernel(const float* __restrict__ in, const float* __restrict__ g,
                   const float* __restrict__ b, float* __restrict__ x)
{
    __shared__ float w1[8], w2[8];
    const int row = blockIdx.x, tid = threadIdx.x;
    const int lane = tid & 31, wid = tid >> 5;
    float v = in[row * DD + tid];

    float s1 = v, s2 = v * v;
    #pragma unroll
    for (int off = 16; off > 0; off >>= 1) {
        s1 += __shfl_xor_sync(0xffffffffu, s1, off);
        s2 += __shfl_xor_sync(0xffffffffu, s2, off);
    }
    if (lane == 0) { w1[wid] = s1; w2[wid] = s2; }
    __syncthreads();
    float t1 = 0.f, t2 = 0.f;
    #pragma unroll
    for (int i = 0; i < 8; i++) { t1 += w1[i]; t2 += w2[i]; }

    float mu = t1 * (1.f / DD);
    float var = t2 * (1.f / DD) - mu * mu;

    float y = (v - mu) * rsqrtf(var + 1e-5f) * g[tid] + b[tid];
    if (ACT == 1) y = act_elu(y);
    x[row * DD + tid] += y;
}

// ---------------- flash attention via tf32 mma.sync ----------------
__global__ __launch_bounds__(128)
void flash_mma_kernel(const float* __restrict__ qkv, float* __restrict__ out)
{
    __shared__ __align__(16) unsigned Ks[64][36];
    __shared__ __align__(16) unsigned Vs[64][36];
    __shared__ __align__(16) unsigned Ps[64][66];

    const int tid = threadIdx.x;
    const int lane = tid & 31;
    const int wid = tid >> 5;
    const int hh = blockIdx.y;
    const int q0 = blockIdx.x * 64;
    const int gr = lane >> 2;
    const int gq = lane & 3;
    const float scale = 0.17677669529663689f;  // 1/sqrt(32)

    const int r0 = wid * 16 + gr;
    const int r1 = r0 + 8;

    unsigned aq[4][4];
    {
        const float* p0 = &qkv[(q0 + r0) * 768 + hh * 32];
        const float* p1 = &qkv[(q0 + r1) * 768 + hh * 32];
        #pragma unroll
        for (int kk = 0; kk < 4; kk++) {
            aq[kk][0] = cvt_tf32(p0[kk * 8 + gq] * scale);
            aq[kk][1] = cvt_tf32(p1[kk * 8 + gq] * scale);
            aq[kk][2] = cvt_tf32(p0[kk * 8 + gq + 4] * scale);
            aq[kk][3] = cvt_tf32(p1[kk * 8 + gq + 4] * scale);
        }
    }

    float m0 = -1e30f, l0 = 0.f, m1 = -1e30f, l1 = 0.f;
    float o[4][4];
    #pragma unroll
    for (int n = 0; n < 4; n++)
        #pragma unroll
        for (int f = 0; f < 4; f++) o[n][f] = 0.f;

    for (int t0 = 0; t0 < NN; t0 += 64) {
        __syncthreads();
        #pragma unroll
        for (int i = tid; i < 512; i += 128) {
            int r = i >> 3, d = (i & 7) * 4;
            float4 kv = *(const float4*)&qkv[(t0 + r) * 768 + 256 + hh * 32 + d];
            float4 vv = *(const float4*)&qkv[(t0 + r) * 768 + 512 + hh * 32 + d];
            uint4 kt, vt;
            kt.x = cvt_tf32(kv.x); kt.y = cvt_tf32(kv.y);
            kt.z = cvt_tf32(kv.z); kt.w = cvt_tf32(kv.w);
            vt.x = cvt_tf32(vv.x); vt.y = cvt_tf32(vv.y);
            vt.z = cvt_tf32(vv.z); vt.w = cvt_tf32(vv.w);
            *(uint4*)&Ks[r][d] = kt;
            *(uint4*)&Vs[r][d] = vt;
        }
        __syncthreads();

        float sc[8][4];
        #pragma unroll
        for (int nn = 0; nn < 8; nn++) {
            sc[nn][0] = 0.f; sc[nn][1] = 0.f; sc[nn][2] = 0.f; sc[nn][3] = 0.f;
            #pragma unroll
            for (int kk = 0; kk < 4; kk++) {
                unsigned b0 = Ks[nn * 8 + gr][kk * 8 + gq];
                unsigned b1 = Ks[nn * 8 + gr][kk * 8 + gq + 4];
                mma_tf32(sc[nn], aq[kk], b0, b1);
            }
        }

        float rmax0 = -1e30f, rmax1 = -1e30f;
        #pragma unroll
        for (int nn = 0; nn < 8; nn++) {
            rmax0 = fmaxf(rmax0, fmaxf(sc[nn][0], sc[nn][1]));
            rmax1 = fmaxf(rmax1, fmaxf(sc[nn][2], sc[nn][3]));
        }
        rmax0 = fmaxf(rmax0, __shfl_xor_sync(0xffffffffu, rmax0, 1));
        rmax0 = fmaxf(rmax0, __shfl_xor_sync(0xffffffffu, rmax0, 2));
        rmax1 = fmaxf(rmax1, __shfl_xor_sync(0xffffffffu, rmax1, 1));
        rmax1 = fmaxf(rmax1, __shfl_xor_sync(0xffffffffu, rmax1, 2));

        float nm0 = fmaxf(m0, rmax0), alpha0 = __expf(m0 - nm0);
        float nm1 = fmaxf(m1, rmax1), alpha1 = __expf(m1 - nm1);

        float ps0 = 0.f, ps1 = 0.f;
        #pragma unroll
        for (int nn = 0; nn < 8; nn++) {
            float p00 = __expf(sc[nn][0] - nm0);
            float p01 = __expf(sc[nn][1] - nm0);
            float p10 = __expf(sc[nn][2] - nm1);
            float p11 = __expf(sc[nn][3] - nm1);
            ps0 += p00 + p01;
            ps1 += p10 + p11;
            uint2 w0, w1;
            w0.x = cvt_tf32(p00); w0.y = cvt_tf32(p01);
            w1.x = cvt_tf32(p10); w1.y = cvt_tf32(p11);
            *(uint2*)&Ps[r0][nn * 8 + 2 * gq] = w0;
            *(uint2*)&Ps[r1][nn * 8 + 2 * gq] = w1;
        }
        ps0 += __shfl_xor_sync(0xffffffffu, ps0, 1);
        ps0 += __shfl_xor_sync(0xffffffffu, ps0, 2);
        ps1 += __shfl_xor_sync(0xffffffffu, ps1, 1);
        ps1 += __shfl_xor_sync(0xffffffffu, ps1, 2);

        l0 = l0 * alpha0 + ps0; m0 = nm0;
        l1 = l1 * alpha1 + ps1; m1 = nm1;

        #pragma unroll
        for (int nn = 0; nn < 4; nn++) {
            o[nn][0] *= alpha0; o[nn][1] *= alpha0;
            o[nn][2] *= alpha1; o[nn][3] *= alpha1;
        }

        __syncwarp();

        #pragma unroll
        for (int kk = 0; kk < 8; kk++) {
            unsigned pa[4];
            pa[0] = Ps[r0][kk * 8 + gq];
            pa[1] = Ps[r1][kk * 8 + gq];
            pa[2] = Ps[r0][kk * 8 + gq + 4];
            pa[3] = Ps[r1][kk * 8 + gq + 4];
            #pragma unroll
            for (int nn = 0; nn < 4; nn++) {
                unsigned b0 = Vs[kk * 8 + gq][nn * 8 + gr];
                unsigned b1 = Vs[kk * 8 + gq + 4][nn * 8 + gr];
                mma_tf32(o[nn], pa, b0, b1);
            }
        }
        __syncwarp();
    }

    const float inv0 = 1.f / l0, inv1 = 1.f / l1;
    #pragma unroll
    for (int nn = 0; nn < 4; nn++) {
        float2 w0, w1;
        w0.x = o[nn][0] * inv0; w0.y = o[nn][1] * inv0;
        w1.x = o[nn][2] * inv1; w1.y = o[nn][3] * inv1;
        *(float2*)&out[(q0 + r0) * DD + hh * 32 + nn * 8 + 2 * gq] = w0;
        *(float2*)&out[(q0 + r1) * DD + hh * 32 + nn * 8 + 2 * gq] = w1;
    }
}

// ---------------- host orchestration ----------------
extern "C" void kernel_launch(void* const* d_in, const int* in_sizes, int n_in,
                              void* d_out, int out_size)
{
    const float*     x         = (const float*)d_in[0];
    const int*       ei        = (const int*)d_in[1];
    const float*     in_w      = (const float*)d_in[2];
    const float*     in_b      = (const float*)d_in[3];
    const float*     head_w1   = (const float*)d_in[4];
    const float*     head_b1   = (const float*)d_in[5];
    const float*     head_w2   = (const float*)d_in[6];
    const float*     head_b2   = (const float*)d_in[7];
    const float*     mlp_w1    = (const float*)d_in[8];
    const float*     mlp_b1    = (const float*)d_in[9];
    const float*     mlp_w2    = (const float*)d_in[10];
    const float*     mlp_b2    = (const float*)d_in[11];
    const float*     gin_eps   = (const float*)d_in[12];
    const float*     ln1_g     = (const float*)d_in[13];
    const float*     ln1_b     = (const float*)d_in[14];
    const float*     attn_in_w = (const float*)d_in[15];
    const float*     attn_in_b = (const float*)d_in[16];
    const float*     attn_out_w= (const float*)d_in[17];
    const float*     attn_out_b= (const float*)d_in[18];
    const float*     ln2_g     = (const float*)d_in[19];
    const float*     ln2_b     = (const float*)d_in[20];
    const float*     ffn_w1    = (const float*)d_in[21];
    const float*     ffn_b1    = (const float*)d_in[22];
    const float*     ffn_w2    = (const float*)d_in[23];
    const float*     ffn_b2    = (const float*)d_in[24];
    const float*     ln3_g     = (const float*)d_in[25];
    const float*     ln3_b     = (const float*)d_in[26];

    float *h, *pre, *t, *t2, *ao, *emb;
    cudaGetSymbolAddress((void**)&h,   g_h);
    cudaGetSymbolAddress((void**)&pre, g_pre);
    cudaGetSymbolAddress((void**)&t,   g_t);
    cudaGetSymbolAddress((void**)&t2,  g_t2);
    cudaGetSymbolAddress((void**)&ao,  g_ao);
    cudaGetSymbolAddress((void**)&emb, g_emb);

    // input proj + ELU
    gemm_mma_kernel<1><<<dim3(DD / 64, NN / 64), 256>>>(x, in_w, in_b, h, NN, DD, DIN);

    for (int l = 0; l < 2; l++) {
        // ---- GIN ----
        gin_init_kernel<<<(NN * DD / 4) / 256, 256>>>(h, gin_eps, l, pre);
        gin_agg_kernel<<<(EE * 64) / 256, 256>>>(ei, h, pre);
        gemm_mma_kernel<1><<<dim3(DD / 64, NN / 64), 256>>>(
            pre, mlp_w1 + (size_t)l * DD * DD, mlp_b1 + (size_t)l * DD, t, NN, DD, DD);
        gemm_mma_kernel<0><<<dim3(DD / 64, NN / 64), 256>>>(
            t, mlp_w2 + (size_t)l * DD * DD, mlp_b2 + (size_t)l * DD, t2, NN, DD, DD);
        ln_res_kernel<1><<<NN, 256>>>(t2, ln1_g + (size_t)l * DD, ln1_b + (size_t)l * DD, h);

        // ---- global attention ----
        gemm_mma_kernel<0><<<dim3(768 / 64, NN / 64), 256>>>(
            h, attn_in_w + (size_t)l * 768 * DD, attn_in_b + (size_t)l * 768, t, NN, 768, DD);
        flash_mma_kernel<<<dim3(NN / 64, HH), 128>>>(t, ao);
        gemm_mma_kernel<0><<<dim3(DD / 64, NN / 64), 256>>>(
            ao, attn_out_w + (size_t)l * DD * DD, attn_out_b + (size_t)l * DD, t2, NN, DD, DD);
        ln_res_kernel<0><<<NN, 256>>>(t2, ln2_g + (size_t)l * DD, ln2_b + (size_t)l * DD, h);

        // ---- FFN ----
        gemm_mma_kernel<2><<<dim3(512 / 64, NN / 64), 256>>>(
            h, ffn_w1 + (size_t)l * 512 * DD, ffn_b1 + (size_t)l * 512, t, NN, 512, DD);
        gemm_mma_kernel<0><<<dim3(DD / 64, NN / 64), 256>>>(
            t, ffn_w2 + (size_t)l * DD * 512, ffn_b2 + (size_t)l * DD, t2, NN, DD, 512);
        ln_res_kernel<0><<<NN, 256>>>(t2, ln3_g + (size_t)l * DD, ln3_b + (size_t)l * DD, h);
    }

    // ---- head ----
    gemm_mma_kernel<1><<<dim3(DEMB / 64, NN / 64), 256>>>(h, head_w1, head_b1, emb, NN, DEMB, DD);
    gemm_kernel<0><<<dim3(1, NN / 64), 256>>>(emb, head_w2, head_b2, (float*)d_out, NN, TT, DEMB);
}

// round 11
// speedup vs baseline: 4.4154x; 1.0456x over previous
#include <cuda_runtime.h>
#include <cuda_bf16.h>
#include <math.h>

#define NN 4096
#define EE 131072
#define DIN 72
#define DD 256
#define HH 8
#define HDD 32
#define DEMB 128
#define TT 5

// ---------------- scratch (device globals; no runtime allocation) ----------------
__device__ float g_h  [NN * DD];
__device__ float g_pre[NN * DD];
__device__ float g_t  [NN * 768];
__device__ float g_t2 [NN * DD];
__device__ float g_ao [NN * DD];
__device__ float g_emb[NN * DEMB];

// ---------------- tf32 mma helpers ----------------
__device__ __forceinline__ unsigned cvt_tf32(float x) {
    unsigned r;
    asm("cvt.rna.tf32.f32 %0, %1;" : "=r"(r) : "f"(x));
    return r;
}
__device__ __forceinline__ void mma_tf32(float* c, const unsigned* a,
                                         unsigned b0, unsigned b1) {
    asm volatile(
        "mma.sync.aligned.m16n8k8.row.col.f32.tf32.tf32.f32 "
        "{%0,%1,%2,%3}, {%4,%5,%6,%7}, {%8,%9}, {%0,%1,%2,%3};\n"
        : "+f"(c[0]), "+f"(c[1]), "+f"(c[2]), "+f"(c[3])
        : "r"(a[0]), "r"(a[1]), "r"(a[2]), "r"(a[3]), "r"(b0), "r"(b1));
}

// ---------------- activations ----------------
__device__ __forceinline__ float act_elu(float v) {
    return v > 0.f ? v : expm1f(v);
}
__device__ __forceinline__ float act_gelu_tanh(float v) {
    const float c = 0.7978845608028654f;   // sqrt(2/pi)
    float u = c * (v + 0.044715f * v * v * v);
    return 0.5f * v * (1.f + tanhf(u));
}

// ---------------- tf32 MMA GEMM: C = act(A @ W^T + b) ----------------
// Block: 256 threads = 8 warps (4x2), tile 64x64, BK=32 (zero-filled tail).
// WPRE: additionally write pre[m*256+n] = (1+eps[0])*C_val  (requires Nout==256).
template <int ACT, bool WPRE>
__global__ __launch_bounds__(256)
void gemm_mma_kernel(const float* __restrict__ A, const float* __restrict__ W,
                     const float* __restrict__ bias, float* __restrict__ C,
                     int M, int Nout, int K,
                     float* __restrict__ pre, const float* __restrict__ eps)
{
    __shared__ __align__(16) unsigned As[2][64][36];
    __shared__ __align__(16) unsigned Bs[2][64][36];

    const int tid = threadIdx.x;
    const int lane = tid & 31;
    const int wid = tid >> 5;
    const int gr = lane >> 2;
    const int gq = lane & 3;
    const int wm = (wid >> 1) * 16;
    const int wn = (wid & 1) * 32;
    const int m0 = blockIdx.y * 64, n0 = blockIdx.x * 64;

    float acc[4][4];
    #pragma unroll
    for (int ni = 0; ni < 4; ni++)
        #pragma unroll
        for (int f = 0; f < 4; f++) acc[ni][f] = 0.f;

    const int KT = (K + 31) >> 5;

    uint4 pa[2], pb[2];

    auto fetch = [&](int kt) {
        #pragma unroll
        for (int u = 0; u < 2; u++) {
            int i = tid + u * 256;
            int r = i >> 3, cg = i & 7;
            int k = kt * 32 + cg * 4;
            uint4 va = {0u, 0u, 0u, 0u}, vb = {0u, 0u, 0u, 0u};
            if (k < K) {
                float4 fa = *(const float4*)&A[(size_t)(m0 + r) * K + k];
                float4 fb = *(const float4*)&W[(size_t)(n0 + r) * K + k];
                va.x = cvt_tf32(fa.x); va.y = cvt_tf32(fa.y);
                va.z = cvt_tf32(fa.z); va.w = cvt_tf32(fa.w);
                vb.x = cvt_tf32(fb.x); vb.y = cvt_tf32(fb.y);
                vb.z = cvt_tf32(fb.z); vb.w = cvt_tf32(fb.w);
            }
            pa[u] = va; pb[u] = vb;
        }
    };
    auto stash = [&](int buf) {
        #pragma unroll
        for (int u = 0; u < 2; u++) {
            int i = tid + u * 256;
            int r = i >> 3, cg = i & 7;
            *(uint4*)&As[buf][r][cg * 4] = pa[u];
            *(uint4*)&Bs[buf][r][cg * 4] = pb[u];
        }
    };

    fetch(0);
    stash(0);
    __syncthreads();

    for (int kt = 0; kt < KT; kt++) {
        const int cur = kt & 1;
        if (kt + 1 < KT) fetch(kt + 1);

        const unsigned (*Ac)[36] = As[cur];
        const unsigned (*Bc)[36] = Bs[cur];
        #pragma unroll
        for (int kk = 0; kk < 4; kk++) {
            unsigned a[4];
            const int rr = wm + gr;
            a[0] = Ac[rr][kk * 8 + gq];
            a[1] = Ac[rr + 8][kk * 8 + gq];
            a[2] = Ac[rr][kk * 8 + gq + 4];
            a[3] = Ac[rr + 8][kk * 8 + gq + 4];
            #pragma unroll
            for (int ni = 0; ni < 4; ni++) {
                unsigned b0 = Bc[wn + ni * 8 + gr][kk * 8 + gq];
                unsigned b1 = Bc[wn + ni * 8 + gr][kk * 8 + gq + 4];
                mma_tf32(acc[ni], a, b0, b1);
            }
        }

        if (kt + 1 < KT) stash(cur ^ 1);
        __syncthreads();
    }

    float s = 1.f;
    if (WPRE) s = 1.f + eps[0];

    const int m = m0 + wm + gr;
    #pragma unroll
    for (int ni = 0; ni < 4; ni++) {
        const int n = n0 + wn + ni * 8 + 2 * gq;
        float b0 = bias[n], b1 = bias[n + 1];
        float2 w0, w1;
        w0.x = acc[ni][0] + b0; w0.y = acc[ni][1] + b1;
        w1.x = acc[ni][2] + b0; w1.y = acc[ni][3] + b1;
        if (ACT == 1) {
            w0.x = act_elu(w0.x); w0.y = act_elu(w0.y);
            w1.x = act_elu(w1.x); w1.y = act_elu(w1.y);
        }
        if (ACT == 2) {
            w0.x = act_gelu_tanh(w0.x); w0.y = act_gelu_tanh(w0.y);
            w1.x = act_gelu_tanh(w1.x); w1.y = act_gelu_tanh(w1.y);
        }
        *(float2*)&C[(size_t)m * Nout + n] = w0;
        *(float2*)&C[(size_t)(m + 8) * Nout + n] = w1;
        if (WPRE) {
            float2 p0, p1;
            p0.x = s * w0.x; p0.y = s * w0.y;
            p1.x = s * w1.x; p1.y = s * w1.y;
            *(float2*)&pre[(size_t)m * 256 + n] = p0;
            *(float2*)&pre[(size_t)(m + 8) * 256 + n] = p1;
        }
    }
}

// ---------------- small fallback SGEMM (N=5 head only) ----------------
template <int ACT>
__global__ __launch_bounds__(256)
void gemm_kernel(const float* __restrict__ A, const float* __restrict__ W,
                 const float* __restrict__ bias, float* __restrict__ C,
                 int M, int Nout, int K)
{
    __shared__ float As[16][64];
    __shared__ float Bs[16][64];
    const int tid = threadIdx.x;
    const int tx = tid & 15, ty = tid >> 4;
    const int m0 = blockIdx.y * 64, n0 = blockIdx.x * 64;

    float acc[4][4] = {};

    for (int k0 = 0; k0 < K; k0 += 16) {
        #pragma unroll
        for (int i = tid; i < 1024; i += 256) {
            int r = i >> 4, kk = i & 15;
            int k = k0 + kk;
            As[kk][r] = (k < K) ? A[(m0 + r) * K + k] : 0.f;
            int n = n0 + r;
            Bs[kk][r] = (n < Nout && k < K) ? W[n * K + k] : 0.f;
        }
        __syncthreads();
        #pragma unroll
        for (int kk = 0; kk < 16; kk++) {
            float4 a = *(const float4*)&As[kk][ty * 4];
            float4 b = *(const float4*)&Bs[kk][tx * 4];
            float av[4] = {a.x, a.y, a.z, a.w};
            float bv[4] = {b.x, b.y, b.z, b.w};
            #pragma unroll
            for (int i = 0; i < 4; i++)
                #pragma unroll
                for (int j = 0; j < 4; j++)
                    acc[i][j] += av[i] * bv[j];
        }
        __syncthreads();
    }

    #pragma unroll
    for (int i = 0; i < 4; i++) {
        int m = m0 + ty * 4 + i;
        #pragma unroll
        for (int j = 0; j < 4; j++) {
            int n = n0 + tx * 4 + j;
            if (n < Nout) {
                float v = acc[i][j] + bias[n];
                if (ACT == 1) v = act_elu(v);
                if (ACT == 2) v = act_gelu_tanh(v);
                C[m * Nout + n] = v;
            }
        }
    }
}

// ---------------- GIN edge aggregation: vector red.global.add.v4.f32 ----------------
__global__ __launch_bounds__(256)
void gin_agg_kernel(const int* __restrict__ ei,
                    const float* __restrict__ x, float* __restrict__ pre)
{
    long long gid = (long long)blockIdx.x * blockDim.x + threadIdx.x;
    int e = (int)(gid >> 6);
    int c = ((int)gid & 63) * 4;
    if (e >= EE) return;
    int src = ei[e];
    int dst = ei[EE + e];
    float4 v = *(const float4*)&x[src * DD + c];
    float* a = &pre[dst * DD + c];
    asm volatile("red.global.add.v4.f32 [%0], {%1, %2, %3, %4};"
                 :: "l"(a), "f"(v.x), "f"(v.y), "f"(v.z), "f"(v.w)
                 : "memory");
}

// ---------------- fused LayerNorm (+opt ELU) + residual, one-pass ----------------
// WPRE: also write pre = (1+eps[0]) * x_new  (for the layer that follows).
template <int ACT, bool WPRE>
__global__ __launch_bounds__(256)
void ln_res_kernel(const float* __restrict__ in, const float* __restrict__ g,
                   const float* __restrict__ b, float* __restrict__ x,
                   float* __restrict__ pre, const float* __restrict__ eps)
{
    __shared__ float w1[8], w2[8];
    const int row = blockIdx.x, tid = threadIdx.x;
    const int lane = tid & 31, wid = tid >> 5;
    float v = in[row * DD + tid];

    float s1 = v, s2 = v * v;
    #pragma unroll
    for (int off = 16; off > 0; off >>= 1) {
        s1 += __shfl_xor_sync(0xffffffffu, s1, off);
        s2 += __shfl_xor_sync(0xffffffffu, s2, off);
    }
    if (lane == 0) { w1[wid] = s1; w2[wid] = s2; }
    __syncthreads();
    float t1 = 0.f, t2 = 0.f;
    #pragma unroll
    for (int i = 0; i < 8; i++) { t1 += w1[i]; t2 += w2[i]; }

    float mu = t1 * (1.f / DD);
    float var = t2 * (1.f / DD) - mu * mu;

    float y = (v - mu) * rsqrtf(var + 1e-5f) * g[tid] + b[tid];
    if (ACT == 1) y = act_elu(y);
    float xn = x[row * DD + tid] + y;
    x[row * DD + tid] = xn;
    if (WPRE) pre[row * DD + tid] = (1.f + eps[0]) * xn;
}

// ---------------- flash attention via tf32 mma.sync, BM=128 ----------------
// Block = 256 threads (8 warps), 128 q-rows; warp w owns rows w*16..w*16+15.
// grid = (N/128, H). Dynamic smem: Ks[64][36] | Vs[64][36] | Ps[128][66].
__global__ __launch_bounds__(256)
void flash_mma_kernel(const float* __restrict__ qkv, float* __restrict__ out)
{
    extern __shared__ __align__(16) unsigned fsm[];
    unsigned (*Ks)[36] = (unsigned(*)[36])fsm;
    unsigned (*Vs)[36] = (unsigned(*)[36])(fsm + 64 * 36);
    unsigned (*Ps)[66] = (unsigned(*)[66])(fsm + 2 * 64 * 36);

    const int tid = threadIdx.x;
    const int lane = tid & 31;
    const int wid = tid >> 5;
    const int hh = blockIdx.y;
    const int q0 = blockIdx.x * 128;
    const int gr = lane >> 2;
    const int gq = lane & 3;
    const float scale = 0.17677669529663689f;  // 1/sqrt(32)

    const int r0 = wid * 16 + gr;   // 0..127
    const int r1 = r0 + 8;

    unsigned aq[4][4];
    {
        const float* p0 = &qkv[(q0 + r0) * 768 + hh * 32];
        const float* p1 = &qkv[(q0 + r1) * 768 + hh * 32];
        #pragma unroll
        for (int kk = 0; kk < 4; kk++) {
            aq[kk][0] = cvt_tf32(p0[kk * 8 + gq] * scale);
            aq[kk][1] = cvt_tf32(p1[kk * 8 + gq] * scale);
            aq[kk][2] = cvt_tf32(p0[kk * 8 + gq + 4] * scale);
            aq[kk][3] = cvt_tf32(p1[kk * 8 + gq + 4] * scale);
        }
    }

    float m0 = -1e30f, l0 = 0.f, m1 = -1e30f, l1 = 0.f;
    float o[4][4];
    #pragma unroll
    for (int n = 0; n < 4; n++)
        #pragma unroll
        for (int f = 0; f < 4; f++) o[n][f] = 0.f;

    for (int t0 = 0; t0 < NN; t0 += 64) {
        __syncthreads();
        #pragma unroll
        for (int i = tid; i < 512; i += 256) {
            int r = i >> 3, d = (i & 7) * 4;
            float4 kv = *(const float4*)&qkv[(t0 + r) * 768 + 256 + hh * 32 + d];
            float4 vv = *(const float4*)&qkv[(t0 + r) * 768 + 512 + hh * 32 + d];
            uint4 kt, vt;
            kt.x = cvt_tf32(kv.x); kt.y = cvt_tf32(kv.y);
            kt.z = cvt_tf32(kv.z); kt.w = cvt_tf32(kv.w);
            vt.x = cvt_tf32(vv.x); vt.y = cvt_tf32(vv.y);
            vt.z = cvt_tf32(vv.z); vt.w = cvt_tf32(vv.w);
            *(uint4*)&Ks[r][d] = kt;
            *(uint4*)&Vs[r][d] = vt;
        }
        __syncthreads();

        float sc[8][4];
        #pragma unroll
        for (int nn = 0; nn < 8; nn++) {
            sc[nn][0] = 0.f; sc[nn][1] = 0.f; sc[nn][2] = 0.f; sc[nn][3] = 0.f;
            #pragma unroll
            for (int kk = 0; kk < 4; kk++) {
                unsigned b0 = Ks[nn * 8 + gr][kk * 8 + gq];
                unsigned b1 = Ks[nn * 8 + gr][kk * 8 + gq + 4];
                mma_tf32(sc[nn], aq[kk], b0, b1);
            }
        }

        float rmax0 = -1e30f, rmax1 = -1e30f;
        #pragma unroll
        for (int nn = 0; nn < 8; nn++) {
            rmax0 = fmaxf(rmax0, fmaxf(sc[nn][0], sc[nn][1]));
            rmax1 = fmaxf(rmax1, fmaxf(sc[nn][2], sc[nn][3]));
        }
        rmax0 = fmaxf(rmax0, __shfl_xor_sync(0xffffffffu, rmax0, 1));
        rmax0 = fmaxf(rmax0, __shfl_xor_sync(0xffffffffu, rmax0, 2));
        rmax1 = fmaxf(rmax1, __shfl_xor_sync(0xffffffffu, rmax1, 1));
        rmax1 = fmaxf(rmax1, __shfl_xor_sync(0xffffffffu, rmax1, 2));

        float nm0 = fmaxf(m0, rmax0), alpha0 = __expf(m0 - nm0);
        float nm1 = fmaxf(m1, rmax1), alpha1 = __expf(m1 - nm1);

        float ps0 = 0.f, ps1 = 0.f;
        #pragma unroll
        for (int nn = 0; nn < 8; nn++) {
            float p00 = __expf(sc[nn][0] - nm0);
            float p01 = __expf(sc[nn][1] - nm0);
            float p10 = __expf(sc[nn][2] - nm1);
            float p11 = __expf(sc[nn][3] - nm1);
            ps0 += p00 + p01;
            ps1 += p10 + p11;
            uint2 w0, w1;
            w0.x = cvt_tf32(p00); w0.y = cvt_tf32(p01);
            w1.x = cvt_tf32(p10); w1.y = cvt_tf32(p11);
            *(uint2*)&Ps[r0][nn * 8 + 2 * gq] = w0;
            *(uint2*)&Ps[r1][nn * 8 + 2 * gq] = w1;
        }
        ps0 += __shfl_xor_sync(0xffffffffu, ps0, 1);
        ps0 += __shfl_xor_sync(0xffffffffu, ps0, 2);
        ps1 += __shfl_xor_sync(0xffffffffu, ps1, 1);
        ps1 += __shfl_xor_sync(0xffffffffu, ps1, 2);

        l0 = l0 * alpha0 + ps0; m0 = nm0;
        l1 = l1 * alpha1 + ps1; m1 = nm1;

        #pragma unroll
        for (int nn = 0; nn < 4; nn++) {
            o[nn][0] *= alpha0; o[nn][1] *= alpha0;
            o[nn][2] *= alpha1; o[nn][3] *= alpha1;
        }

        __syncwarp();

        #pragma unroll
        for (int kk = 0; kk < 8; kk++) {
            unsigned pa[4];
            pa[0] = Ps[r0][kk * 8 + gq];
            pa[1] = Ps[r1][kk * 8 + gq];
            pa[2] = Ps[r0][kk * 8 + gq + 4];
            pa[3] = Ps[r1][kk * 8 + gq + 4];
            #pragma unroll
            for (int nn = 0; nn < 4; nn++) {
                unsigned b0 = Vs[kk * 8 + gq][nn * 8 + gr];
                unsigned b1 = Vs[kk * 8 + gq + 4][nn * 8 + gr];
                mma_tf32(o[nn], pa, b0, b1);
            }
        }
        __syncwarp();
    }

    const float inv0 = 1.f / l0, inv1 = 1.f / l1;
    #pragma unroll
    for (int nn = 0; nn < 4; nn++) {
        float2 w0, w1;
        w0.x = o[nn][0] * inv0; w0.y = o[nn][1] * inv0;
        w1.x = o[nn][2] * inv1; w1.y = o[nn][3] * inv1;
        *(float2*)&out[(q0 + r0) * DD + hh * 32 + nn * 8 + 2 * gq] = w0;
        *(float2*)&out[(q0 + r1) * DD + hh * 32 + nn * 8 + 2 * gq] = w1;
    }
}

// ---------------- host orchestration ----------------
extern "C" void kernel_launch(void* const* d_in, const int* in_sizes, int n_in,
                              void* d_out, int out_size)
{
    const float*     x         = (const float*)d_in[0];
    const int*       ei        = (const int*)d_in[1];
    const float*     in_w      = (const float*)d_in[2];
    const float*     in_b      = (const float*)d_in[3];
    const float*     head_w1   = (const float*)d_in[4];
    const float*     head_b1   = (const float*)d_in[5];
    const float*     head_w2   = (const float*)d_in[6];
    const float*     head_b2   = (const float*)d_in[7];
    const float*     mlp_w1    = (const float*)d_in[8];
    const float*     mlp_b1    = (const float*)d_in[9];
    const float*     mlp_w2    = (const float*)d_in[10];
    const float*     mlp_b2    = (const float*)d_in[11];
    const float*     gin_eps   = (const float*)d_in[12];
    const float*     ln1_g     = (const float*)d_in[13];
    const float*     ln1_b     = (const float*)d_in[14];
    const float*     attn_in_w = (const float*)d_in[15];
    const float*     attn_in_b = (const float*)d_in[16];
    const float*     attn_out_w= (const float*)d_in[17];
    const float*     attn_out_b= (const float*)d_in[18];
    const float*     ln2_g     = (const float*)d_in[19];
    const float*     ln2_b     = (const float*)d_in[20];
    const float*     ffn_w1    = (const float*)d_in[21];
    const float*     ffn_b1    = (const float*)d_in[22];
    const float*     ffn_w2    = (const float*)d_in[23];
    const float*     ffn_b2    = (const float*)d_in[24];
    const float*     ln3_g     = (const float*)d_in[25];
    const float*     ln3_b     = (const float*)d_in[26];

    float *h, *pre, *t, *t2, *ao, *emb;
    cudaGetSymbolAddress((void**)&h,   g_h);
    cudaGetSymbolAddress((void**)&pre, g_pre);
    cudaGetSymbolAddress((void**)&t,   g_t);
    cudaGetSymbolAddress((void**)&t2,  g_t2);
    cudaGetSymbolAddress((void**)&ao,  g_ao);
    cudaGetSymbolAddress((void**)&emb, g_emb);

    const int FLASH_SMEM = (2 * 64 * 36 + 128 * 66) * 4;   // 52224 B
    cudaFuncSetAttribute(flash_mma_kernel,
                         cudaFuncAttributeMaxDynamicSharedMemorySize, FLASH_SMEM);

    // input proj + ELU; also writes pre = (1+eps[0]) * h  (GIN of layer 0)
    gemm_mma_kernel<1, true><<<dim3(DD / 64, NN / 64), 256>>>(
        x, in_w, in_b, h, NN, DD, DIN, pre, gin_eps);

    for (int l = 0; l < 2; l++) {
        // ---- GIN: pre already holds (1+eps_l)*h; add neighbor sums ----
        gin_agg_kernel<<<(EE * 64) / 256, 256>>>(ei, h, pre);
        gemm_mma_kernel<1, false><<<dim3(DD / 64, NN / 64), 256>>>(
            pre, mlp_w1 + (size_t)l * DD * DD, mlp_b1 + (size_t)l * DD, t, NN, DD, DD,
            nullptr, nullptr);
        gemm_mma_kernel<0, false><<<dim3(DD / 64, NN / 64), 256>>>(
            t, mlp_w2 + (size_t)l * DD * DD, mlp_b2 + (size_t)l * DD, t2, NN, DD, DD,
            nullptr, nullptr);
        ln_res_kernel<1, false><<<NN, 256>>>(
            t2, ln1_g + (size_t)l * DD, ln1_b + (size_t)l * DD, h, nullptr, nullptr);

        // ---- global attention ----
        gemm_mma_kernel<0, false><<<dim3(768 / 64, NN / 64), 256>>>(
            h, attn_in_w + (size_t)l * 768 * DD, attn_in_b + (size_t)l * 768, t, NN, 768, DD,
            nullptr, nullptr);
        flash_mma_kernel<<<dim3(NN / 128, HH), 256, FLASH_SMEM>>>(t, ao);
        gemm_mma_kernel<0, false><<<dim3(DD / 64, NN / 64), 256>>>(
            ao, attn_out_w + (size_t)l * DD * DD, attn_out_b + (size_t)l * DD, t2, NN, DD, DD,
            nullptr, nullptr);
        ln_res_kernel<0, false><<<NN, 256>>>(
            t2, ln2_g + (size_t)l * DD, ln2_b + (size_t)l * DD, h, nullptr, nullptr);

        // ---- FFN ----
        gemm_mma_kernel<2, false><<<dim3(512 / 64, NN / 64), 256>>>(
            h, ffn_w1 + (size_t)l * 512 * DD, ffn_b1 + (size_t)l * 512, t, NN, 512, DD,
            nullptr, nullptr);
        gemm_mma_kernel<0, false><<<dim3(DD / 64, NN / 64), 256>>>(
            t, ffn_w2 + (size_t)l * DD * 512, ffn_b2 + (size_t)l * DD, t2, NN, DD, 512,
            nullptr, nullptr);
        if (l == 0) {
            // also seed pre for layer 1's GIN: pre = (1+eps[1]) * h_new
            ln_res_kernel<0, true><<<NN, 256>>>(
                t2, ln3_g, ln3_b, h, pre, gin_eps + 1);
        } else {
            ln_res_kernel<0, false><<<NN, 256>>>(
                t2, ln3_g + (size_t)l * DD, ln3_b + (size_t)l * DD, h, nullptr, nullptr);
        }
    }

    // ---- head ----
    gemm_mma_kernel<1, false><<<dim3(DEMB / 64, NN / 64), 256>>>(
        h, head_w1, head_b1, emb, NN, DEMB, DD, nullptr, nullptr);
    gemm_kernel<0><<<dim3(1, NN / 64), 256>>>(emb, head_w2, head_b2, (float*)d_out, NN, TT, DEMB);
}